// round 1
// baseline (speedup 1.0000x reference)
#include <cuda_runtime.h>
#include <cuda_bf16.h>

// ---------------------------------------------------------------------------
// Problem constants
// ---------------------------------------------------------------------------
#define BS_N        8192
#define NUM_CLASSES 400
#define DIM         768
#define M_TOTAL     (2 * BS_N)          // 16384 rows of image_embed / logits
#define LOGITS_ELEMS (M_TOTAL * NUM_CLASSES)

// ---------------------------------------------------------------------------
// Mask kernel: one block per image row i; tid[0:256) -> box 0, [256:512) -> box 1
// Replicates _get_mask (double bilinear) + _get_att_mask (2x2 avgpool, top-25
// keep with jax.lax.top_k stable tie-breaking, 2x upsample).
// ---------------------------------------------------------------------------
__device__ __forceinline__ float bilin14(const float* __restrict__ m,
                                         float Y, float X, float eH, float eW) {
    float sy = fmaxf((Y + 0.5f) * 14.0f / eH - 0.5f, 0.0f);
    float sx = fmaxf((X + 0.5f) * 14.0f / eW - 0.5f, 0.0f);
    float r0f = floorf(sy);
    float c0f = floorf(sx);
    int r0 = (int)r0f;
    int c0 = (int)c0f;
    int r1 = min(r0 + 1, 13);
    int c1 = min(c0 + 1, 13);
    float fy = sy - r0f;
    float fx = sx - c0f;
    float g00 = m[r0 * 14 + c0];
    float g01 = m[r0 * 14 + c1];
    float g10 = m[r1 * 14 + c0];
    float g11 = m[r1 * 14 + c1];
    return g00 * (1.0f - fy) * (1.0f - fx)
         + g01 * (1.0f - fy) * fx
         + g10 * fy * (1.0f - fx)
         + g11 * fy * fx;
}

__global__ void __launch_bounds__(512) mask_kernel(const float* __restrict__ attn,
                                                   const int* __restrict__ pos,
                                                   float* __restrict__ mask_out) {
    const int i   = blockIdx.x;     // image row 0..8191
    const int tid = threadIdx.x;    // 0..511
    const int box = tid >> 8;       // 0 or 1
    const int t   = tid & 255;      // 0..255 (196 active)

    __shared__ float m14[196];
    __shared__ float cm[2][196];
    __shared__ float a7[2][49];
    __shared__ int   keep[2][49];

    if (tid < 196) m14[tid] = attn[i * 196 + tid];

    const int* p = pos + i * 12;
    const int o0 = p[box * 4 + 0];
    const int o1 = p[box * 4 + 1];
    const int o2 = p[box * 4 + 2];
    const int o3 = p[box * 4 + 3];
    const int e0 = p[8], e1 = p[9], e2 = p[10], e3 = p[11];

    __syncthreads();

    if (t < 196) {
        const int y = t / 14;
        const int x = t % 14;
        const float oH   = (float)o2;
        const float oW   = (float)o3;
        const float top  = (float)(o0 - e0);
        const float left = (float)(o1 - e1);
        const float eH   = (float)e2;
        const float eW   = (float)e3;

        float ty  = fmaxf(((float)y + 0.5f) * oH / 14.0f - 0.5f, 0.0f);
        float y0  = floorf(ty);
        float y1  = fminf(y0 + 1.0f, oH - 1.0f);
        float wy  = ty - y0;
        float tx  = fmaxf(((float)x + 0.5f) * oW / 14.0f - 0.5f, 0.0f);
        float x0  = floorf(tx);
        float x1  = fminf(x0 + 1.0f, oW - 1.0f);
        float wx  = tx - x0;

        float Y0 = top + y0,  Y1 = top + y1;
        float X0 = left + x0, X1 = left + x1;

        float v00 = bilin14(m14, Y0, X0, eH, eW);
        float v01 = bilin14(m14, Y0, X1, eH, eW);
        float v10 = bilin14(m14, Y1, X0, eH, eW);
        float v11 = bilin14(m14, Y1, X1, eH, eW);

        cm[box][t] = v00 * (1.0f - wy) * (1.0f - wx)
                   + v01 * (1.0f - wy) * wx
                   + v10 * wy * (1.0f - wx)
                   + v11 * wy * wx;
    }
    __syncthreads();

    if (t < 49) {
        const int qy = t / 7;
        const int qx = t % 7;
        const float* c = cm[box];
        float s = (c[(2 * qy) * 14 + 2 * qx] + c[(2 * qy) * 14 + 2 * qx + 1]
                 + c[(2 * qy + 1) * 14 + 2 * qx] + c[(2 * qy + 1) * 14 + 2 * qx + 1]) * 0.25f;
        a7[box][t] = s;
    }
    __syncthreads();

    if (t < 49) {
        const float v = a7[box][t];
        int rank = 0;
        #pragma unroll
        for (int j = 0; j < 49; ++j) {
            float u = a7[box][j];
            rank += (u > v) || (u == v && j < t);   // stable top_k tie-break
        }
        keep[box][t] = (rank < 25);                  // int(49*0.5)+1 = 25 kept
    }
    __syncthreads();

    if (t < 196) {
        const int y = t / 14;
        const int x = t % 14;
        const int q = (y >> 1) * 7 + (x >> 1);
        mask_out[(box * BS_N + i) * 196 + t] = keep[box][q] ? 0.0f : 1.0f;
    }
}

// ---------------------------------------------------------------------------
// FP32 SGEMM: C[16384,400] = A[16384,768] * W[400,768]^T + b
// BM=128, BN=80 (5 exact N-tiles), BK=16, 256 threads, 8x5 per-thread tile.
// ---------------------------------------------------------------------------
#define BM 128
#define BN 80
#define BK 16

__global__ void __launch_bounds__(256) gemm_kernel(const float* __restrict__ A,
                                                   const float* __restrict__ Wm,
                                                   const float* __restrict__ bias,
                                                   float* __restrict__ C) {
    __shared__ float As[BK][BM];
    __shared__ float Bs[BK][BN];

    const int tid = threadIdx.x;
    const int m0  = blockIdx.x * BM;
    const int n0  = blockIdx.y * BN;
    const int tm  = (tid >> 4) * 8;   // 0..120
    const int tn  = (tid & 15) * 5;   // 0..75

    float acc[8][5];
    #pragma unroll
    for (int u = 0; u < 8; ++u)
        #pragma unroll
        for (int v = 0; v < 5; ++v)
            acc[u][v] = 0.0f;

    for (int k0 = 0; k0 < DIM; k0 += BK) {
        // Load A tile: 128x16 = 512 float4, 2 per thread
        #pragma unroll
        for (int r = 0; r < 2; ++r) {
            int f   = tid + r * 256;
            int row = f >> 2;
            int kq  = (f & 3) * 4;
            float4 v = *reinterpret_cast<const float4*>(&A[(m0 + row) * DIM + k0 + kq]);
            As[kq + 0][row] = v.x;
            As[kq + 1][row] = v.y;
            As[kq + 2][row] = v.z;
            As[kq + 3][row] = v.w;
        }
        // Load B tile (W rows as columns): 80x16 = 320 float4
        {
            int f   = tid;
            int row = f >> 2;
            int kq  = (f & 3) * 4;
            float4 v = *reinterpret_cast<const float4*>(&Wm[(n0 + row) * DIM + k0 + kq]);
            Bs[kq + 0][row] = v.x;
            Bs[kq + 1][row] = v.y;
            Bs[kq + 2][row] = v.z;
            Bs[kq + 3][row] = v.w;
            if (tid < 64) {
                f   = tid + 256;
                row = f >> 2;
                kq  = (f & 3) * 4;
                v   = *reinterpret_cast<const float4*>(&Wm[(n0 + row) * DIM + k0 + kq]);
                Bs[kq + 0][row] = v.x;
                Bs[kq + 1][row] = v.y;
                Bs[kq + 2][row] = v.z;
                Bs[kq + 3][row] = v.w;
            }
        }
        __syncthreads();

        #pragma unroll
        for (int k = 0; k < BK; ++k) {
            float a[8], bv[5];
            #pragma unroll
            for (int u = 0; u < 8; ++u) a[u] = As[k][tm + u];
            #pragma unroll
            for (int v = 0; v < 5; ++v) bv[v] = Bs[k][tn + v];
            #pragma unroll
            for (int u = 0; u < 8; ++u)
                #pragma unroll
                for (int v = 0; v < 5; ++v)
                    acc[u][v] = fmaf(a[u], bv[v], acc[u][v]);
        }
        __syncthreads();
    }

    #pragma unroll
    for (int v = 0; v < 5; ++v) {
        float bb = bias[n0 + tn + v];
        #pragma unroll
        for (int u = 0; u < 8; ++u) {
            C[(m0 + tm + u) * NUM_CLASSES + n0 + tn + v] = acc[u][v] + bb;
        }
    }
}

// ---------------------------------------------------------------------------
// Launch
// ---------------------------------------------------------------------------
extern "C" void kernel_launch(void* const* d_in, const int* in_sizes, int n_in,
                              void* d_out, int out_size) {
    const float* attn        = (const float*)d_in[0];   // [8192, 196]
    const int*   pos         = (const int*)d_in[1];     // [8192, 3, 4]
    const float* image_embed = (const float*)d_in[2];   // [16384, 768]
    const float* Wm          = (const float*)d_in[3];   // [400, 768]
    const float* bias        = (const float*)d_in[4];   // [400]

    float* logits = (float*)d_out;                      // [16384, 400]
    float* mask   = (float*)d_out + LOGITS_ELEMS;       // [16384, 196]

    dim3 gemm_grid(M_TOTAL / BM, NUM_CLASSES / BN);     // 128 x 5
    gemm_kernel<<<gemm_grid, 256>>>(image_embed, Wm, bias, logits);

    mask_kernel<<<BS_N, 512>>>(attn, pos, mask);
}

// round 3
// speedup vs baseline: 1.8945x; 1.8945x over previous
#include <cuda_runtime.h>
#include <cuda_bf16.h>
#include <cstdint>

// ---------------------------------------------------------------------------
// Problem constants
// ---------------------------------------------------------------------------
#define BS_N        8192
#define NUM_CLASSES 400
#define DIM         768
#define M_TOTAL     (2 * BS_N)          // 16384 rows
#define LOGITS_ELEMS (M_TOTAL * NUM_CLASSES)

// ---------------------------------------------------------------------------
// Scratch: bf16 hi/lo splits of A (image_embed) and W
// ---------------------------------------------------------------------------
__device__ __nv_bfloat16 g_Ahi[(size_t)M_TOTAL * DIM];
__device__ __nv_bfloat16 g_Alo[(size_t)M_TOTAL * DIM];
__device__ __nv_bfloat16 g_Whi[(size_t)NUM_CLASSES * DIM];
__device__ __nv_bfloat16 g_Wlo[(size_t)NUM_CLASSES * DIM];

// ---------------------------------------------------------------------------
// Split kernel: fp32 -> (bf16 hi, bf16 lo)
// ---------------------------------------------------------------------------
__global__ void __launch_bounds__(256) split_kernel(const float* __restrict__ in,
                                                    int n, int which) {
    int i4 = (blockIdx.x * 256 + threadIdx.x) * 4;
    if (i4 >= n) return;
    __nv_bfloat16* hi = which ? g_Whi : g_Ahi;
    __nv_bfloat16* lo = which ? g_Wlo : g_Alo;

    float4 v = *reinterpret_cast<const float4*>(in + i4);
    __nv_bfloat16 h0 = __float2bfloat16(v.x);
    __nv_bfloat16 h1 = __float2bfloat16(v.y);
    __nv_bfloat16 h2 = __float2bfloat16(v.z);
    __nv_bfloat16 h3 = __float2bfloat16(v.w);
    __nv_bfloat16 l0 = __float2bfloat16(v.x - __bfloat162float(h0));
    __nv_bfloat16 l1 = __float2bfloat16(v.y - __bfloat162float(h1));
    __nv_bfloat16 l2 = __float2bfloat16(v.z - __bfloat162float(h2));
    __nv_bfloat16 l3 = __float2bfloat16(v.w - __bfloat162float(h3));

    *reinterpret_cast<__nv_bfloat162*>(hi + i4)     = __halves2bfloat162(h0, h1);
    *reinterpret_cast<__nv_bfloat162*>(hi + i4 + 2) = __halves2bfloat162(h2, h3);
    *reinterpret_cast<__nv_bfloat162*>(lo + i4)     = __halves2bfloat162(l0, l1);
    *reinterpret_cast<__nv_bfloat162*>(lo + i4 + 2) = __halves2bfloat162(l2, l3);
}

// ---------------------------------------------------------------------------
// HMMA GEMM: C[16384,400] = A @ W^T + b   (3-term bf16 split, fp32 accum)
// CTA 128x80x32, 8 warps (4m x 2n), warp tile 32x40 (2 x 5 mma tiles m16n8k16)
// cp.async double-buffered SMEM, stride padded to 40 bf16 (conflict-free).
// ---------------------------------------------------------------------------
#define BM 128
#define BN 80
#define BK 32
#define KSTRIDE 40                       // padded k-stride (elements)
#define NKITERS (DIM / BK)               // 24

// per-stage SMEM byte offsets
#define SA_H 0
#define SA_L (SA_H + BM * KSTRIDE * 2)   // 10240
#define SB_H (SA_L + BM * KSTRIDE * 2)   // 20480
#define SB_L (SB_H + BN * KSTRIDE * 2)   // 26880
#define STAGE_B (SB_L + BN * KSTRIDE * 2) // 33280
#define SMEM_GEMM_TOTAL (2 * STAGE_B)    // 66560

__device__ __forceinline__ uint32_t smem_u32(const void* p) {
    uint32_t a;
    asm("{ .reg .u64 t; cvta.to.shared.u64 t, %1; cvt.u32.u64 %0, t; }"
        : "=r"(a) : "l"(p));
    return a;
}

__device__ __forceinline__ void cp_async16(uint32_t s, const void* g) {
    asm volatile("cp.async.cg.shared.global [%0], [%1], 16;" :: "r"(s), "l"(g));
}

__device__ __forceinline__ void cp_commit() {
    asm volatile("cp.async.commit_group;" ::: "memory");
}

template <int N>
__device__ __forceinline__ void cp_wait() {
    asm volatile("cp.async.wait_group %0;" :: "n"(N) : "memory");
}

__device__ __forceinline__ void mma16816(float* c, uint32_t a0, uint32_t a1,
                                         uint32_t a2, uint32_t a3,
                                         uint32_t b0, uint32_t b1) {
    asm volatile(
        "mma.sync.aligned.m16n8k16.row.col.f32.bf16.bf16.f32 "
        "{%0,%1,%2,%3}, {%4,%5,%6,%7}, {%8,%9}, {%0,%1,%2,%3};"
        : "+f"(c[0]), "+f"(c[1]), "+f"(c[2]), "+f"(c[3])
        : "r"(a0), "r"(a1), "r"(a2), "r"(a3), "r"(b0), "r"(b1));
}

__device__ __forceinline__ void load_stage(uint32_t sbase,
                                           const __nv_bfloat16* Ah,
                                           const __nv_bfloat16* Al,
                                           const __nv_bfloat16* Bh,
                                           const __nv_bfloat16* Bl,
                                           int k0, int tid) {
    // A tiles: 128 rows x 32 k = 512 x 16B chunks each (2 per thread)
    #pragma unroll
    for (int r = 0; r < 2; ++r) {
        int idx = tid + r * 256;
        int row = idx >> 2;
        int seg = idx & 3;                 // 4 segments of 8 bf16
        size_t goff = (size_t)row * DIM + k0 + seg * 8;
        uint32_t soff = (uint32_t)(row * KSTRIDE + seg * 8) * 2;
        cp_async16(sbase + SA_H + soff, Ah + goff);
        cp_async16(sbase + SA_L + soff, Al + goff);
    }
    // B tiles: 80 rows x 32 k = 320 x 16B chunks each
    {
        int idx = tid;
        int row = idx >> 2;
        int seg = idx & 3;
        size_t goff = (size_t)row * DIM + k0 + seg * 8;
        uint32_t soff = (uint32_t)(row * KSTRIDE + seg * 8) * 2;
        cp_async16(sbase + SB_H + soff, Bh + goff);
        cp_async16(sbase + SB_L + soff, Bl + goff);
        if (tid < 64) {
            idx = tid + 256;
            row = idx >> 2;
            seg = idx & 3;
            goff = (size_t)row * DIM + k0 + seg * 8;
            soff = (uint32_t)(row * KSTRIDE + seg * 8) * 2;
            cp_async16(sbase + SB_H + soff, Bh + goff);
            cp_async16(sbase + SB_L + soff, Bl + goff);
        }
    }
    cp_commit();
}

__global__ void __launch_bounds__(256, 2) gemm_hmma_kernel(const float* __restrict__ bias,
                                                           float* __restrict__ C) {
    extern __shared__ char smem[];
    const int tid    = threadIdx.x;
    const int warp   = tid >> 5;
    const int lane   = tid & 31;
    const int warp_m = warp >> 1;          // 0..3
    const int warp_n = warp & 1;           // 0..1
    const uint32_t sb = smem_u32(smem);

    const int m0 = blockIdx.x * BM;
    const int n0 = blockIdx.y * BN;

    const __nv_bfloat16* Ah = g_Ahi + (size_t)m0 * DIM;
    const __nv_bfloat16* Al = g_Alo + (size_t)m0 * DIM;
    const __nv_bfloat16* Bh = g_Whi + (size_t)n0 * DIM;
    const __nv_bfloat16* Bl = g_Wlo + (size_t)n0 * DIM;

    float acc[2][5][4];
    #pragma unroll
    for (int mt = 0; mt < 2; ++mt)
        #pragma unroll
        for (int nt = 0; nt < 5; ++nt)
            #pragma unroll
            for (int j = 0; j < 4; ++j)
                acc[mt][nt][j] = 0.0f;

    // fragment base offsets (bytes) within a stage
    const int fr = lane >> 2;              // 0..7
    const int fc = (lane & 3) * 2;         // 0,2,4,6

    load_stage(sb, Ah, Al, Bh, Bl, 0, tid);

    for (int c = 0; c < NKITERS; ++c) {
        const uint32_t cur = sb + (c & 1) * STAGE_B;
        if (c + 1 < NKITERS) {
            load_stage(sb + ((c + 1) & 1) * STAGE_B, Ah, Al, Bh, Bl,
                       (c + 1) * BK, tid);
            cp_wait<1>();
        } else {
            cp_wait<0>();
        }
        __syncthreads();

        #pragma unroll
        for (int kk = 0; kk < BK; kk += 16) {
            // A fragments (hi & lo) for 2 m-tiles
            uint32_t ah[2][4], al[2][4];
            #pragma unroll
            for (int mt = 0; mt < 2; ++mt) {
                int rb = warp_m * 32 + mt * 16;
                uint32_t o00 = cur + ((rb + fr)     * KSTRIDE + kk + fc)     * 2;
                uint32_t o10 = cur + ((rb + fr + 8) * KSTRIDE + kk + fc)     * 2;
                uint32_t o01 = cur + ((rb + fr)     * KSTRIDE + kk + fc + 8) * 2;
                uint32_t o11 = cur + ((rb + fr + 8) * KSTRIDE + kk + fc + 8) * 2;
                asm volatile("ld.shared.b32 %0, [%1];" : "=r"(ah[mt][0]) : "r"(o00 + SA_H));
                asm volatile("ld.shared.b32 %0, [%1];" : "=r"(ah[mt][1]) : "r"(o10 + SA_H));
                asm volatile("ld.shared.b32 %0, [%1];" : "=r"(ah[mt][2]) : "r"(o01 + SA_H));
                asm volatile("ld.shared.b32 %0, [%1];" : "=r"(ah[mt][3]) : "r"(o11 + SA_H));
                asm volatile("ld.shared.b32 %0, [%1];" : "=r"(al[mt][0]) : "r"(o00 + SA_L));
                asm volatile("ld.shared.b32 %0, [%1];" : "=r"(al[mt][1]) : "r"(o10 + SA_L));
                asm volatile("ld.shared.b32 %0, [%1];" : "=r"(al[mt][2]) : "r"(o01 + SA_L));
                asm volatile("ld.shared.b32 %0, [%1];" : "=r"(al[mt][3]) : "r"(o11 + SA_L));
            }
            // B fragments (hi & lo) for 5 n-tiles
            uint32_t bh[5][2], bl[5][2];
            #pragma unroll
            for (int nt = 0; nt < 5; ++nt) {
                int nb = warp_n * 40 + nt * 8 + fr;
                uint32_t o0 = cur + (nb * KSTRIDE + kk + fc)     * 2;
                uint32_t o1 = cur + (nb * KSTRIDE + kk + fc + 8) * 2;
                asm volatile("ld.shared.b32 %0, [%1];" : "=r"(bh[nt][0]) : "r"(o0 + SB_H));
                asm volatile("ld.shared.b32 %0, [%1];" : "=r"(bh[nt][1]) : "r"(o1 + SB_H));
                asm volatile("ld.shared.b32 %0, [%1];" : "=r"(bl[nt][0]) : "r"(o0 + SB_L));
                asm volatile("ld.shared.b32 %0, [%1];" : "=r"(bl[nt][1]) : "r"(o1 + SB_L));
            }
            // 3-term MMAs
            #pragma unroll
            for (int mt = 0; mt < 2; ++mt)
                #pragma unroll
                for (int nt = 0; nt < 5; ++nt) {
                    mma16816(acc[mt][nt], ah[mt][0], ah[mt][1], ah[mt][2], ah[mt][3],
                             bh[nt][0], bh[nt][1]);
                    mma16816(acc[mt][nt], ah[mt][0], ah[mt][1], ah[mt][2], ah[mt][3],
                             bl[nt][0], bl[nt][1]);
                    mma16816(acc[mt][nt], al[mt][0], al[mt][1], al[mt][2], al[mt][3],
                             bh[nt][0], bh[nt][1]);
                }
        }
        __syncthreads();
    }

    // Epilogue: write C with bias
    #pragma unroll
    for (int mt = 0; mt < 2; ++mt) {
        int row = m0 + warp_m * 32 + mt * 16 + fr;
        #pragma unroll
        for (int nt = 0; nt < 5; ++nt) {
            int col = n0 + warp_n * 40 + nt * 8 + fc;
            float b0 = __ldg(bias + col);
            float b1 = __ldg(bias + col + 1);
            float2 v0 = make_float2(acc[mt][nt][0] + b0, acc[mt][nt][1] + b1);
            float2 v1 = make_float2(acc[mt][nt][2] + b0, acc[mt][nt][3] + b1);
            *reinterpret_cast<float2*>(&C[(size_t)row * NUM_CLASSES + col]) = v0;
            *reinterpret_cast<float2*>(&C[(size_t)(row + 8) * NUM_CLASSES + col]) = v1;
        }
    }
}

// ---------------------------------------------------------------------------
// Mask kernel (UNCHANGED: exact FP ordering protects top-k tie decisions)
// ---------------------------------------------------------------------------
__device__ __forceinline__ float bilin14(const float* __restrict__ m,
                                         float Y, float X, float eH, float eW) {
    float sy = fmaxf((Y + 0.5f) * 14.0f / eH - 0.5f, 0.0f);
    float sx = fmaxf((X + 0.5f) * 14.0f / eW - 0.5f, 0.0f);
    float r0f = floorf(sy);
    float c0f = floorf(sx);
    int r0 = (int)r0f;
    int c0 = (int)c0f;
    int r1 = min(r0 + 1, 13);
    int c1 = min(c0 + 1, 13);
    float fy = sy - r0f;
    float fx = sx - c0f;
    float g00 = m[r0 * 14 + c0];
    float g01 = m[r0 * 14 + c1];
    float g10 = m[r1 * 14 + c0];
    float g11 = m[r1 * 14 + c1];
    return g00 * (1.0f - fy) * (1.0f - fx)
         + g01 * (1.0f - fy) * fx
         + g10 * fy * (1.0f - fx)
         + g11 * fy * fx;
}

__global__ void __launch_bounds__(512) mask_kernel(const float* __restrict__ attn,
                                                   const int* __restrict__ pos,
                                                   float* __restrict__ mask_out) {
    const int i   = blockIdx.x;
    const int tid = threadIdx.x;
    const int box = tid >> 8;
    const int t   = tid & 255;

    __shared__ float m14[196];
    __shared__ float cm[2][196];
    __shared__ float a7[2][49];
    __shared__ int   keep[2][49];

    if (tid < 196) m14[tid] = attn[i * 196 + tid];

    const int* p = pos + i * 12;
    const int o0 = p[box * 4 + 0];
    const int o1 = p[box * 4 + 1];
    const int o2 = p[box * 4 + 2];
    const int o3 = p[box * 4 + 3];
    const int e0 = p[8], e1 = p[9], e2 = p[10], e3 = p[11];

    __syncthreads();

    if (t < 196) {
        const int y = t / 14;
        const int x = t % 14;
        const float oH   = (float)o2;
        const float oW   = (float)o3;
        const float top  = (float)(o0 - e0);
        const float left = (float)(o1 - e1);
        const float eH   = (float)e2;
        const float eW   = (float)e3;

        float ty  = fmaxf(((float)y + 0.5f) * oH / 14.0f - 0.5f, 0.0f);
        float y0  = floorf(ty);
        float y1  = fminf(y0 + 1.0f, oH - 1.0f);
        float wy  = ty - y0;
        float tx  = fmaxf(((float)x + 0.5f) * oW / 14.0f - 0.5f, 0.0f);
        float x0  = floorf(tx);
        float x1  = fminf(x0 + 1.0f, oW - 1.0f);
        float wx  = tx - x0;

        float Y0 = top + y0,  Y1 = top + y1;
        float X0 = left + x0, X1 = left + x1;

        float v00 = bilin14(m14, Y0, X0, eH, eW);
        float v01 = bilin14(m14, Y0, X1, eH, eW);
        float v10 = bilin14(m14, Y1, X0, eH, eW);
        float v11 = bilin14(m14, Y1, X1, eH, eW);

        cm[box][t] = v00 * (1.0f - wy) * (1.0f - wx)
                   + v01 * (1.0f - wy) * wx
                   + v10 * wy * (1.0f - wx)
                   + v11 * wy * wx;
    }
    __syncthreads();

    if (t < 49) {
        const int qy = t / 7;
        const int qx = t % 7;
        const float* c = cm[box];
        float s = (c[(2 * qy) * 14 + 2 * qx] + c[(2 * qy) * 14 + 2 * qx + 1]
                 + c[(2 * qy + 1) * 14 + 2 * qx] + c[(2 * qy + 1) * 14 + 2 * qx + 1]) * 0.25f;
        a7[box][t] = s;
    }
    __syncthreads();

    if (t < 49) {
        const float v = a7[box][t];
        int rank = 0;
        #pragma unroll
        for (int j = 0; j < 49; ++j) {
            float u = a7[box][j];
            rank += (u > v) || (u == v && j < t);
        }
        keep[box][t] = (rank < 25);
    }
    __syncthreads();

    if (t < 196) {
        const int y = t / 14;
        const int x = t % 14;
        const int q = (y >> 1) * 7 + (x >> 1);
        mask_out[(box * BS_N + i) * 196 + t] = keep[box][q] ? 0.0f : 1.0f;
    }
}

// ---------------------------------------------------------------------------
// Launch
// ---------------------------------------------------------------------------
extern "C" void kernel_launch(void* const* d_in, const int* in_sizes, int n_in,
                              void* d_out, int out_size) {
    const float* attn        = (const float*)d_in[0];   // [8192, 196]
    const int*   pos         = (const int*)d_in[1];     // [8192, 3, 4]
    const float* image_embed = (const float*)d_in[2];   // [16384, 768]
    const float* Wm          = (const float*)d_in[3];   // [400, 768]
    const float* bias        = (const float*)d_in[4];   // [400]

    float* logits = (float*)d_out;                      // [16384, 400]
    float* mask   = (float*)d_out + LOGITS_ELEMS;       // [16384, 196]

    cudaFuncSetAttribute(gemm_hmma_kernel,
                         cudaFuncAttributeMaxDynamicSharedMemorySize,
                         SMEM_GEMM_TOTAL);

    // Split A and W into bf16 hi/lo
    {
        int nA = M_TOTAL * DIM;
        split_kernel<<<(nA / 4 + 255) / 256, 256>>>(image_embed, nA, 0);
        int nW = NUM_CLASSES * DIM;
        split_kernel<<<(nW / 4 + 255) / 256, 256>>>(Wm, nW, 1);
    }

    // Tensor-core GEMM (HMMA mma.sync)
    dim3 ggrid(M_TOTAL / BM, NUM_CLASSES / BN);          // 128 x 5
    gemm_hmma_kernel<<<ggrid, 256, SMEM_GEMM_TOTAL>>>(bias, logits);

    // Mask path
    mask_kernel<<<BS_N, 512>>>(attn, pos, mask);
}

// round 5
// speedup vs baseline: 1.9826x; 1.0465x over previous
#include <cuda_runtime.h>
#include <cuda_bf16.h>
#include <cstdint>

// ---------------------------------------------------------------------------
// Problem constants
// ---------------------------------------------------------------------------
#define BS_N        8192
#define NUM_CLASSES 400
#define DIM         768
#define M_TOTAL     (2 * BS_N)          // 16384 rows
#define LOGITS_ELEMS (M_TOTAL * NUM_CLASSES)

// ---------------------------------------------------------------------------
// Scratch: bf16 hi/lo splits of A (image_embed) and W
// ---------------------------------------------------------------------------
__device__ __nv_bfloat16 g_Ahi[(size_t)M_TOTAL * DIM];
__device__ __nv_bfloat16 g_Alo[(size_t)M_TOTAL * DIM];
__device__ __nv_bfloat16 g_Whi[(size_t)NUM_CLASSES * DIM];
__device__ __nv_bfloat16 g_Wlo[(size_t)NUM_CLASSES * DIM];

// ---------------------------------------------------------------------------
// Split kernel: fp32 -> (bf16 hi, bf16 lo), 8 elems / thread, 16B stores
// ---------------------------------------------------------------------------
__global__ void __launch_bounds__(256) split_kernel(const float* __restrict__ in,
                                                    int n, int which) {
    int i8 = (blockIdx.x * 256 + threadIdx.x) * 8;
    if (i8 >= n) return;
    __nv_bfloat16* hi = which ? g_Whi : g_Ahi;
    __nv_bfloat16* lo = which ? g_Wlo : g_Alo;

    float4 v0 = *reinterpret_cast<const float4*>(in + i8);
    float4 v1 = *reinterpret_cast<const float4*>(in + i8 + 4);

    float f[8] = {v0.x, v0.y, v0.z, v0.w, v1.x, v1.y, v1.z, v1.w};
    __nv_bfloat16 h[8], l[8];
    #pragma unroll
    for (int j = 0; j < 8; ++j) {
        h[j] = __float2bfloat16(f[j]);
        l[j] = __float2bfloat16(f[j] - __bfloat162float(h[j]));
    }
    *reinterpret_cast<uint4*>(hi + i8) = *reinterpret_cast<const uint4*>(h);
    *reinterpret_cast<uint4*>(lo + i8) = *reinterpret_cast<const uint4*>(l);
}

// ---------------------------------------------------------------------------
// HMMA GEMM: C[16384,400] = A @ W^T + b   (3-term bf16 split, fp32 accum)
// CTA 128x80x32, 8 warps (4m x 2n), 3-stage cp.async pipeline.
// Grid: x = n-blocks (5) FAST so the 5 CTAs sharing one A m-tile run in the
// same wave -> A re-reads hit L2 instead of DRAM.
// ---------------------------------------------------------------------------
#define BM 128
#define BN 80
#define BK 32
#define KSTRIDE 40                        // padded k-stride (elements)
#define NKITERS (DIM / BK)                // 24
#define NSTAGES 3

#define SA_H 0
#define SA_L (SA_H + BM * KSTRIDE * 2)    // 10240
#define SB_H (SA_L + BM * KSTRIDE * 2)    // 20480
#define SB_L (SB_H + BN * KSTRIDE * 2)    // 26880
#define STAGE_B (SB_L + BN * KSTRIDE * 2) // 33280
#define SMEM_GEMM_TOTAL (NSTAGES * STAGE_B) // 99840

__device__ __forceinline__ uint32_t smem_u32(const void* p) {
    uint32_t a;
    asm("{ .reg .u64 t; cvta.to.shared.u64 t, %1; cvt.u32.u64 %0, t; }"
        : "=r"(a) : "l"(p));
    return a;
}

__device__ __forceinline__ void cp_async16(uint32_t s, const void* g) {
    asm volatile("cp.async.cg.shared.global [%0], [%1], 16;" :: "r"(s), "l"(g));
}

__device__ __forceinline__ void cp_commit() {
    asm volatile("cp.async.commit_group;" ::: "memory");
}

template <int N>
__device__ __forceinline__ void cp_wait() {
    asm volatile("cp.async.wait_group %0;" :: "n"(N) : "memory");
}

__device__ __forceinline__ void mma16816(float* c, uint32_t a0, uint32_t a1,
                                         uint32_t a2, uint32_t a3,
                                         uint32_t b0, uint32_t b1) {
    asm volatile(
        "mma.sync.aligned.m16n8k16.row.col.f32.bf16.bf16.f32 "
        "{%0,%1,%2,%3}, {%4,%5,%6,%7}, {%8,%9}, {%0,%1,%2,%3};"
        : "+f"(c[0]), "+f"(c[1]), "+f"(c[2]), "+f"(c[3])
        : "r"(a0), "r"(a1), "r"(a2), "r"(a3), "r"(b0), "r"(b1));
}

__device__ __forceinline__ void load_stage(uint32_t sbase,
                                           const __nv_bfloat16* Ah,
                                           const __nv_bfloat16* Al,
                                           const __nv_bfloat16* Bh,
                                           const __nv_bfloat16* Bl,
                                           int k0, int tid) {
    #pragma unroll
    for (int r = 0; r < 2; ++r) {
        int idx = tid + r * 256;
        int row = idx >> 2;
        int seg = idx & 3;
        size_t goff = (size_t)row * DIM + k0 + seg * 8;
        uint32_t soff = (uint32_t)(row * KSTRIDE + seg * 8) * 2;
        cp_async16(sbase + SA_H + soff, Ah + goff);
        cp_async16(sbase + SA_L + soff, Al + goff);
    }
    {
        int idx = tid;
        int row = idx >> 2;
        int seg = idx & 3;
        size_t goff = (size_t)row * DIM + k0 + seg * 8;
        uint32_t soff = (uint32_t)(row * KSTRIDE + seg * 8) * 2;
        cp_async16(sbase + SB_H + soff, Bh + goff);
        cp_async16(sbase + SB_L + soff, Bl + goff);
        if (tid < 64) {
            idx = tid + 256;
            row = idx >> 2;
            seg = idx & 3;
            goff = (size_t)row * DIM + k0 + seg * 8;
            soff = (uint32_t)(row * KSTRIDE + seg * 8) * 2;
            cp_async16(sbase + SB_H + soff, Bh + goff);
            cp_async16(sbase + SB_L + soff, Bl + goff);
        }
    }
    cp_commit();
}

__global__ void __launch_bounds__(256, 2) gemm_hmma_kernel(const float* __restrict__ bias,
                                                           float* __restrict__ C) {
    extern __shared__ char smem[];
    const int tid    = threadIdx.x;
    const int warp   = tid >> 5;
    const int lane   = tid & 31;
    const int warp_m = warp >> 1;
    const int warp_n = warp & 1;
    const uint32_t sb = smem_u32(smem);

    const int m0 = blockIdx.y * BM;      // y = m (slow)
    const int n0 = blockIdx.x * BN;      // x = n (fast) -> L2 reuse of A

    const __nv_bfloat16* Ah = g_Ahi + (size_t)m0 * DIM;
    const __nv_bfloat16* Al = g_Alo + (size_t)m0 * DIM;
    const __nv_bfloat16* Bh = g_Whi + (size_t)n0 * DIM;
    const __nv_bfloat16* Bl = g_Wlo + (size_t)n0 * DIM;

    float acc[2][5][4];
    #pragma unroll
    for (int mt = 0; mt < 2; ++mt)
        #pragma unroll
        for (int nt = 0; nt < 5; ++nt)
            #pragma unroll
            for (int j = 0; j < 4; ++j)
                acc[mt][nt][j] = 0.0f;

    const int fr = lane >> 2;
    const int fc = (lane & 3) * 2;

    load_stage(sb,             Ah, Al, Bh, Bl, 0,  tid);
    load_stage(sb + STAGE_B,   Ah, Al, Bh, Bl, BK, tid);

    int cur_s = 0;
    for (int c = 0; c < NKITERS; ++c) {
        const uint32_t cur = sb + cur_s * STAGE_B;
        if (c + 2 < NKITERS) {
            int nxt = cur_s + 2; if (nxt >= NSTAGES) nxt -= NSTAGES;
            load_stage(sb + nxt * STAGE_B, Ah, Al, Bh, Bl, (c + 2) * BK, tid);
            cp_wait<2>();
        } else if (c + 1 < NKITERS) {
            cp_wait<1>();
        } else {
            cp_wait<0>();
        }
        __syncthreads();

        #pragma unroll
        for (int kk = 0; kk < BK; kk += 16) {
            uint32_t ah[2][4], al[2][4];
            #pragma unroll
            for (int mt = 0; mt < 2; ++mt) {
                int rb = warp_m * 32 + mt * 16;
                uint32_t o00 = cur + ((rb + fr)     * KSTRIDE + kk + fc)     * 2;
                uint32_t o10 = cur + ((rb + fr + 8) * KSTRIDE + kk + fc)     * 2;
                uint32_t o01 = cur + ((rb + fr)     * KSTRIDE + kk + fc + 8) * 2;
                uint32_t o11 = cur + ((rb + fr + 8) * KSTRIDE + kk + fc + 8) * 2;
                asm volatile("ld.shared.b32 %0, [%1];" : "=r"(ah[mt][0]) : "r"(o00 + SA_H));
                asm volatile("ld.shared.b32 %0, [%1];" : "=r"(ah[mt][1]) : "r"(o10 + SA_H));
                asm volatile("ld.shared.b32 %0, [%1];" : "=r"(ah[mt][2]) : "r"(o01 + SA_H));
                asm volatile("ld.shared.b32 %0, [%1];" : "=r"(ah[mt][3]) : "r"(o11 + SA_H));
                asm volatile("ld.shared.b32 %0, [%1];" : "=r"(al[mt][0]) : "r"(o00 + SA_L));
                asm volatile("ld.shared.b32 %0, [%1];" : "=r"(al[mt][1]) : "r"(o10 + SA_L));
                asm volatile("ld.shared.b32 %0, [%1];" : "=r"(al[mt][2]) : "r"(o01 + SA_L));
                asm volatile("ld.shared.b32 %0, [%1];" : "=r"(al[mt][3]) : "r"(o11 + SA_L));
            }
            uint32_t bh[5][2], bl[5][2];
            #pragma unroll
            for (int nt = 0; nt < 5; ++nt) {
                int nb = warp_n * 40 + nt * 8 + fr;
                uint32_t o0 = cur + (nb * KSTRIDE + kk + fc)     * 2;
                uint32_t o1 = cur + (nb * KSTRIDE + kk + fc + 8) * 2;
                asm volatile("ld.shared.b32 %0, [%1];" : "=r"(bh[nt][0]) : "r"(o0 + SB_H));
                asm volatile("ld.shared.b32 %0, [%1];" : "=r"(bh[nt][1]) : "r"(o1 + SB_H));
                asm volatile("ld.shared.b32 %0, [%1];" : "=r"(bl[nt][0]) : "r"(o0 + SB_L));
                asm volatile("ld.shared.b32 %0, [%1];" : "=r"(bl[nt][1]) : "r"(o1 + SB_L));
            }
            #pragma unroll
            for (int mt = 0; mt < 2; ++mt)
                #pragma unroll
                for (int nt = 0; nt < 5; ++nt) {
                    mma16816(acc[mt][nt], ah[mt][0], ah[mt][1], ah[mt][2], ah[mt][3],
                             bh[nt][0], bh[nt][1]);
                    mma16816(acc[mt][nt], ah[mt][0], ah[mt][1], ah[mt][2], ah[mt][3],
                             bl[nt][0], bl[nt][1]);
                    mma16816(acc[mt][nt], al[mt][0], al[mt][1], al[mt][2], al[mt][3],
                             bh[nt][0], bh[nt][1]);
                }
        }
        __syncthreads();
        if (++cur_s >= NSTAGES) cur_s = 0;
    }

    #pragma unroll
    for (int mt = 0; mt < 2; ++mt) {
        int row = m0 + warp_m * 32 + mt * 16 + fr;
        #pragma unroll
        for (int nt = 0; nt < 5; ++nt) {
            int col = n0 + warp_n * 40 + nt * 8 + fc;
            float b0 = __ldg(bias + col);
            float b1 = __ldg(bias + col + 1);
            float2 v0 = make_float2(acc[mt][nt][0] + b0, acc[mt][nt][1] + b1);
            float2 v1 = make_float2(acc[mt][nt][2] + b0, acc[mt][nt][3] + b1);
            *reinterpret_cast<float2*>(&C[(size_t)row * NUM_CLASSES + col]) = v0;
            *reinterpret_cast<float2*>(&C[(size_t)(row + 8) * NUM_CLASSES + col]) = v1;
        }
    }
}

// ---------------------------------------------------------------------------
// Mask kernel — separable precompute of interpolation weights/indices.
// Every FP expression is source-identical to the round-1/3 (passing) version,
// so results are bit-identical; divides drop from 1568/image to 168/image.
// ---------------------------------------------------------------------------
__device__ __forceinline__ float bilin_combine(const float* __restrict__ m,
                                               int r0, int r1, int c0, int c1,
                                               float fy, float fx) {
    float g00 = m[r0 * 14 + c0];
    float g01 = m[r0 * 14 + c1];
    float g10 = m[r1 * 14 + c0];
    float g11 = m[r1 * 14 + c1];
    return g00 * (1.0f - fy) * (1.0f - fx)
         + g01 * (1.0f - fy) * fx
         + g10 * fy * (1.0f - fx)
         + g11 * fy * fx;
}

__global__ void __launch_bounds__(512) mask_kernel(const float* __restrict__ attn,
                                                   const int* __restrict__ pos,
                                                   float* __restrict__ mask_out) {
    const int i   = blockIdx.x;
    const int tid = threadIdx.x;

    __shared__ float m14[196];
    __shared__ float cm[2][196];
    __shared__ float a7[2][49];
    __shared__ int   keep[2][49];
    __shared__ float t_w[2][2][14];
    __shared__ float t_f0[2][2][14];
    __shared__ float t_f1[2][2][14];
    __shared__ int   t_i00[2][2][14];
    __shared__ int   t_i01[2][2][14];
    __shared__ int   t_i10[2][2][14];
    __shared__ int   t_i11[2][2][14];

    if (tid < 196) m14[tid] = attn[i * 196 + tid];

    // Phase A: 56 threads (warps 14-15) build weight/index tables.
    if (tid >= 448 && tid < 504) {
        const int s    = tid - 448;          // 0..55
        const int pbox = s / 28;             // 0,1
        const int rem  = s - pbox * 28;
        const int axis = rem / 14;           // 0 = y, 1 = x
        const int idx  = rem - axis * 14;

        const int* p = pos + i * 12;
        const int oT = p[pbox * 4 + 0];
        const int oL = p[pbox * 4 + 1];
        const int oHi = p[pbox * 4 + 2];
        const int oWi = p[pbox * 4 + 3];
        const int e0 = p[8], e1 = p[9], e2 = p[10], e3 = p[11];

        const float dimO = axis ? (float)oWi : (float)oHi;
        const float off  = axis ? (float)(oL - e1) : (float)(oT - e0);
        const float dimE = axis ? (float)e3 : (float)e2;

        float ty = fmaxf(((float)idx + 0.5f) * dimO / 14.0f - 0.5f, 0.0f);
        float y0 = floorf(ty);
        float y1 = fminf(y0 + 1.0f, dimO - 1.0f);
        t_w[pbox][axis][idx] = ty - y0;
        float Y0 = off + y0;
        float Y1 = off + y1;

        {
            float sy  = fmaxf((Y0 + 0.5f) * 14.0f / dimE - 0.5f, 0.0f);
            float r0f = floorf(sy);
            int r0 = (int)r0f;
            int r1 = min(r0 + 1, 13);
            t_f0[pbox][axis][idx]  = sy - r0f;
            t_i00[pbox][axis][idx] = r0;
            t_i01[pbox][axis][idx] = r1;
        }
        {
            float sy  = fmaxf((Y1 + 0.5f) * 14.0f / dimE - 0.5f, 0.0f);
            float r0f = floorf(sy);
            int r0 = (int)r0f;
            int r1 = min(r0 + 1, 13);
            t_f1[pbox][axis][idx]  = sy - r0f;
            t_i10[pbox][axis][idx] = r0;
            t_i11[pbox][axis][idx] = r1;
        }
    }
    __syncthreads();

    const int box = tid >> 8;
    const int t   = tid & 255;

    if (t < 196) {
        const int y = t / 14;
        const int x = t % 14;

        float wy  = t_w[box][0][y];
        float wx  = t_w[box][1][x];
        float fyA = t_f0[box][0][y], fyB = t_f1[box][0][y];
        float fxA = t_f0[box][1][x], fxB = t_f1[box][1][x];
        int rA0 = t_i00[box][0][y], rA1 = t_i01[box][0][y];
        int rB0 = t_i10[box][0][y], rB1 = t_i11[box][0][y];
        int cA0 = t_i00[box][1][x], cA1 = t_i01[box][1][x];
        int cB0 = t_i10[box][1][x], cB1 = t_i11[box][1][x];

        float v00 = bilin_combine(m14, rA0, rA1, cA0, cA1, fyA, fxA);
        float v01 = bilin_combine(m14, rA0, rA1, cB0, cB1, fyA, fxB);
        float v10 = bilin_combine(m14, rB0, rB1, cA0, cA1, fyB, fxA);
        float v11 = bilin_combine(m14, rB0, rB1, cB0, cB1, fyB, fxB);

        cm[box][t] = v00 * (1.0f - wy) * (1.0f - wx)
                   + v01 * (1.0f - wy) * wx
                   + v10 * wy * (1.0f - wx)
                   + v11 * wy * wx;
    }
    __syncthreads();

    if (t < 49) {
        const int qy = t / 7;
        const int qx = t % 7;
        const float* c = cm[box];
        float s = (c[(2 * qy) * 14 + 2 * qx] + c[(2 * qy) * 14 + 2 * qx + 1]
                 + c[(2 * qy + 1) * 14 + 2 * qx] + c[(2 * qy + 1) * 14 + 2 * qx + 1]) * 0.25f;
        a7[box][t] = s;
    }
    __syncthreads();

    if (t < 49) {
        const float v = a7[box][t];
        int rank = 0;
        #pragma unroll
        for (int j = 0; j < 49; ++j) {
            float u = a7[box][j];
            rank += (u > v) || (u == v && j < t);
        }
        keep[box][t] = (rank < 25);
    }
    __syncthreads();

    if (t < 196) {
        const int y = t / 14;
        const int x = t % 14;
        const int q = (y >> 1) * 7 + (x >> 1);
        mask_out[(box * BS_N + i) * 196 + t] = keep[box][q] ? 0.0f : 1.0f;
    }
}

// ---------------------------------------------------------------------------
// Launch
// ---------------------------------------------------------------------------
extern "C" void kernel_launch(void* const* d_in, const int* in_sizes, int n_in,
                              void* d_out, int out_size) {
    const float* attn        = (const float*)d_in[0];   // [8192, 196]
    const int*   pos         = (const int*)d_in[1];     // [8192, 3, 4]
    const float* image_embed = (const float*)d_in[2];   // [16384, 768]
    const float* Wm          = (const float*)d_in[3];   // [400, 768]
    const float* bias        = (const float*)d_in[4];   // [400]

    float* logits = (float*)d_out;                      // [16384, 400]
    float* mask   = (float*)d_out + LOGITS_ELEMS;       // [16384, 196]

    cudaFuncSetAttribute(gemm_hmma_kernel,
                         cudaFuncAttributeMaxDynamicSharedMemorySize,
                         SMEM_GEMM_TOTAL);

    {
        int nA = M_TOTAL * DIM;                          // divisible by 8
        split_kernel<<<(nA / 8 + 255) / 256, 256>>>(image_embed, nA, 0);
        int nW = NUM_CLASSES * DIM;
        split_kernel<<<(nW / 8 + 255) / 256, 256>>>(Wm, nW, 1);
    }

    dim3 ggrid(NUM_CLASSES / BN, M_TOTAL / BM);          // x=n (5), y=m (128)
    gemm_hmma_kernel<<<ggrid, 256, SMEM_GEMM_TOTAL>>>(bias, logits);

    mask_kernel<<<BS_N, 512>>>(attn, pos, mask);
}

// round 6
// speedup vs baseline: 2.0514x; 1.0347x over previous
#include <cuda_runtime.h>
#include <cuda_bf16.h>
#include <cstdint>

// ---------------------------------------------------------------------------
// Problem constants
// ---------------------------------------------------------------------------
#define BS_N        8192
#define NUM_CLASSES 400
#define DIM         768
#define M_TOTAL     (2 * BS_N)          // 16384 rows
#define LOGITS_ELEMS (M_TOTAL * NUM_CLASSES)

// ---------------------------------------------------------------------------
// Scratch: bf16 hi/lo splits of A (image_embed) and W
// ---------------------------------------------------------------------------
__device__ __nv_bfloat16 g_Ahi[(size_t)M_TOTAL * DIM];
__device__ __nv_bfloat16 g_Alo[(size_t)M_TOTAL * DIM];
__device__ __nv_bfloat16 g_Whi[(size_t)NUM_CLASSES * DIM];
__device__ __nv_bfloat16 g_Wlo[(size_t)NUM_CLASSES * DIM];

// ---------------------------------------------------------------------------
// Split kernel: fp32 -> (bf16 hi, bf16 lo), 8 elems / thread, 16B stores
// ---------------------------------------------------------------------------
__global__ void __launch_bounds__(256) split_kernel(const float* __restrict__ in,
                                                    int n, int which) {
    int i8 = (blockIdx.x * 256 + threadIdx.x) * 8;
    if (i8 >= n) return;
    __nv_bfloat16* hi = which ? g_Whi : g_Ahi;
    __nv_bfloat16* lo = which ? g_Wlo : g_Alo;

    float4 v0 = *reinterpret_cast<const float4*>(in + i8);
    float4 v1 = *reinterpret_cast<const float4*>(in + i8 + 4);

    float f[8] = {v0.x, v0.y, v0.z, v0.w, v1.x, v1.y, v1.z, v1.w};
    __nv_bfloat16 h[8], l[8];
    #pragma unroll
    for (int j = 0; j < 8; ++j) {
        h[j] = __float2bfloat16(f[j]);
        l[j] = __float2bfloat16(f[j] - __bfloat162float(h[j]));
    }
    *reinterpret_cast<uint4*>(hi + i8) = *reinterpret_cast<const uint4*>(h);
    *reinterpret_cast<uint4*>(lo + i8) = *reinterpret_cast<const uint4*>(l);
}

// ---------------------------------------------------------------------------
// HMMA GEMM: C[16384,400] = A @ W^T + b   (3-term bf16 split, fp32 accum)
// CTA 128x80x32, 8 warps (4m x 2n), 3-stage cp.async pipeline.
// ---------------------------------------------------------------------------
#define BM 128
#define BN 80
#define BK 32
#define KSTRIDE 40                        // padded k-stride (elements)
#define NKITERS (DIM / BK)                // 24
#define NSTAGES 3

#define SA_H 0
#define SA_L (SA_H + BM * KSTRIDE * 2)    // 10240
#define SB_H (SA_L + BM * KSTRIDE * 2)    // 20480
#define SB_L (SB_H + BN * KSTRIDE * 2)    // 26880
#define STAGE_B (SB_L + BN * KSTRIDE * 2) // 33280
#define SMEM_GEMM_TOTAL (NSTAGES * STAGE_B) // 99840

__device__ __forceinline__ uint32_t smem_u32(const void* p) {
    uint32_t a;
    asm("{ .reg .u64 t; cvta.to.shared.u64 t, %1; cvt.u32.u64 %0, t; }"
        : "=r"(a) : "l"(p));
    return a;
}

__device__ __forceinline__ void cp_async16(uint32_t s, const void* g) {
    asm volatile("cp.async.cg.shared.global [%0], [%1], 16;" :: "r"(s), "l"(g));
}

__device__ __forceinline__ void cp_commit() {
    asm volatile("cp.async.commit_group;" ::: "memory");
}

template <int N>
__device__ __forceinline__ void cp_wait() {
    asm volatile("cp.async.wait_group %0;" :: "n"(N) : "memory");
}

__device__ __forceinline__ void mma16816(float* c, uint32_t a0, uint32_t a1,
                                         uint32_t a2, uint32_t a3,
                                         uint32_t b0, uint32_t b1) {
    asm volatile(
        "mma.sync.aligned.m16n8k16.row.col.f32.bf16.bf16.f32 "
        "{%0,%1,%2,%3}, {%4,%5,%6,%7}, {%8,%9}, {%0,%1,%2,%3};"
        : "+f"(c[0]), "+f"(c[1]), "+f"(c[2]), "+f"(c[3])
        : "r"(a0), "r"(a1), "r"(a2), "r"(a3), "r"(b0), "r"(b1));
}

__device__ __forceinline__ void load_stage(uint32_t sbase,
                                           const __nv_bfloat16* Ah,
                                           const __nv_bfloat16* Al,
                                           const __nv_bfloat16* Bh,
                                           const __nv_bfloat16* Bl,
                                           int k0, int tid) {
    #pragma unroll
    for (int r = 0; r < 2; ++r) {
        int idx = tid + r * 256;
        int row = idx >> 2;
        int seg = idx & 3;
        size_t goff = (size_t)row * DIM + k0 + seg * 8;
        uint32_t soff = (uint32_t)(row * KSTRIDE + seg * 8) * 2;
        cp_async16(sbase + SA_H + soff, Ah + goff);
        cp_async16(sbase + SA_L + soff, Al + goff);
    }
    {
        int idx = tid;
        int row = idx >> 2;
        int seg = idx & 3;
        size_t goff = (size_t)row * DIM + k0 + seg * 8;
        uint32_t soff = (uint32_t)(row * KSTRIDE + seg * 8) * 2;
        cp_async16(sbase + SB_H + soff, Bh + goff);
        cp_async16(sbase + SB_L + soff, Bl + goff);
        if (tid < 64) {
            idx = tid + 256;
            row = idx >> 2;
            seg = idx & 3;
            goff = (size_t)row * DIM + k0 + seg * 8;
            soff = (uint32_t)(row * KSTRIDE + seg * 8) * 2;
            cp_async16(sbase + SB_H + soff, Bh + goff);
            cp_async16(sbase + SB_L + soff, Bl + goff);
        }
    }
    cp_commit();
}

__global__ void __launch_bounds__(256, 2) gemm_hmma_kernel(const float* __restrict__ bias,
                                                           float* __restrict__ C) {
    extern __shared__ char smem[];
    const int tid    = threadIdx.x;
    const int warp   = tid >> 5;
    const int lane   = tid & 31;
    const int warp_m = warp >> 1;
    const int warp_n = warp & 1;
    const uint32_t sb = smem_u32(smem);

    const int m0 = blockIdx.y * BM;
    const int n0 = blockIdx.x * BN;

    const __nv_bfloat16* Ah = g_Ahi + (size_t)m0 * DIM;
    const __nv_bfloat16* Al = g_Alo + (size_t)m0 * DIM;
    const __nv_bfloat16* Bh = g_Whi + (size_t)n0 * DIM;
    const __nv_bfloat16* Bl = g_Wlo + (size_t)n0 * DIM;

    float acc[2][5][4];
    #pragma unroll
    for (int mt = 0; mt < 2; ++mt)
        #pragma unroll
        for (int nt = 0; nt < 5; ++nt)
            #pragma unroll
            for (int j = 0; j < 4; ++j)
                acc[mt][nt][j] = 0.0f;

    const int fr = lane >> 2;
    const int fc = (lane & 3) * 2;

    load_stage(sb,             Ah, Al, Bh, Bl, 0,  tid);
    load_stage(sb + STAGE_B,   Ah, Al, Bh, Bl, BK, tid);

    int cur_s = 0;
    for (int c = 0; c < NKITERS; ++c) {
        const uint32_t cur = sb + cur_s * STAGE_B;
        if (c + 2 < NKITERS) {
            int nxt = cur_s + 2; if (nxt >= NSTAGES) nxt -= NSTAGES;
            load_stage(sb + nxt * STAGE_B, Ah, Al, Bh, Bl, (c + 2) * BK, tid);
            cp_wait<2>();
        } else if (c + 1 < NKITERS) {
            cp_wait<1>();
        } else {
            cp_wait<0>();
        }
        __syncthreads();

        #pragma unroll
        for (int kk = 0; kk < BK; kk += 16) {
            uint32_t ah[2][4], al[2][4];
            #pragma unroll
            for (int mt = 0; mt < 2; ++mt) {
                int rb = warp_m * 32 + mt * 16;
                uint32_t o00 = cur + ((rb + fr)     * KSTRIDE + kk + fc)     * 2;
                uint32_t o10 = cur + ((rb + fr + 8) * KSTRIDE + kk + fc)     * 2;
                uint32_t o01 = cur + ((rb + fr)     * KSTRIDE + kk + fc + 8) * 2;
                uint32_t o11 = cur + ((rb + fr + 8) * KSTRIDE + kk + fc + 8) * 2;
                asm volatile("ld.shared.b32 %0, [%1];" : "=r"(ah[mt][0]) : "r"(o00 + SA_H));
                asm volatile("ld.shared.b32 %0, [%1];" : "=r"(ah[mt][1]) : "r"(o10 + SA_H));
                asm volatile("ld.shared.b32 %0, [%1];" : "=r"(ah[mt][2]) : "r"(o01 + SA_H));
                asm volatile("ld.shared.b32 %0, [%1];" : "=r"(ah[mt][3]) : "r"(o11 + SA_H));
                asm volatile("ld.shared.b32 %0, [%1];" : "=r"(al[mt][0]) : "r"(o00 + SA_L));
                asm volatile("ld.shared.b32 %0, [%1];" : "=r"(al[mt][1]) : "r"(o10 + SA_L));
                asm volatile("ld.shared.b32 %0, [%1];" : "=r"(al[mt][2]) : "r"(o01 + SA_L));
                asm volatile("ld.shared.b32 %0, [%1];" : "=r"(al[mt][3]) : "r"(o11 + SA_L));
            }
            uint32_t bh[5][2], bl[5][2];
            #pragma unroll
            for (int nt = 0; nt < 5; ++nt) {
                int nb = warp_n * 40 + nt * 8 + fr;
                uint32_t o0 = cur + (nb * KSTRIDE + kk + fc)     * 2;
                uint32_t o1 = cur + (nb * KSTRIDE + kk + fc + 8) * 2;
                asm volatile("ld.shared.b32 %0, [%1];" : "=r"(bh[nt][0]) : "r"(o0 + SB_H));
                asm volatile("ld.shared.b32 %0, [%1];" : "=r"(bh[nt][1]) : "r"(o1 + SB_H));
                asm volatile("ld.shared.b32 %0, [%1];" : "=r"(bl[nt][0]) : "r"(o0 + SB_L));
                asm volatile("ld.shared.b32 %0, [%1];" : "=r"(bl[nt][1]) : "r"(o1 + SB_L));
            }
            #pragma unroll
            for (int mt = 0; mt < 2; ++mt)
                #pragma unroll
                for (int nt = 0; nt < 5; ++nt) {
                    mma16816(acc[mt][nt], ah[mt][0], ah[mt][1], ah[mt][2], ah[mt][3],
                             bh[nt][0], bh[nt][1]);
                    mma16816(acc[mt][nt], ah[mt][0], ah[mt][1], ah[mt][2], ah[mt][3],
                             bl[nt][0], bl[nt][1]);
                    mma16816(acc[mt][nt], al[mt][0], al[mt][1], al[mt][2], al[mt][3],
                             bh[nt][0], bh[nt][1]);
                }
        }
        __syncthreads();
        if (++cur_s >= NSTAGES) cur_s = 0;
    }

    #pragma unroll
    for (int mt = 0; mt < 2; ++mt) {
        int row = m0 + warp_m * 32 + mt * 16 + fr;
        #pragma unroll
        for (int nt = 0; nt < 5; ++nt) {
            int col = n0 + warp_n * 40 + nt * 8 + fc;
            float b0 = __ldg(bias + col);
            float b1 = __ldg(bias + col + 1);
            float2 v0 = make_float2(acc[mt][nt][0] + b0, acc[mt][nt][1] + b1);
            float2 v1 = make_float2(acc[mt][nt][2] + b0, acc[mt][nt][3] + b1);
            *reinterpret_cast<float2*>(&C[(size_t)row * NUM_CLASSES + col]) = v0;
            *reinterpret_cast<float2*>(&C[(size_t)(row + 8) * NUM_CLASSES + col]) = v1;
        }
    }
}

// ---------------------------------------------------------------------------
// Mask kernel (UNCHANGED from round 5 — bit-exact verified)
// ---------------------------------------------------------------------------
__device__ __forceinline__ float bilin_combine(const float* __restrict__ m,
                                               int r0, int r1, int c0, int c1,
                                               float fy, float fx) {
    float g00 = m[r0 * 14 + c0];
    float g01 = m[r0 * 14 + c1];
    float g10 = m[r1 * 14 + c0];
    float g11 = m[r1 * 14 + c1];
    return g00 * (1.0f - fy) * (1.0f - fx)
         + g01 * (1.0f - fy) * fx
         + g10 * fy * (1.0f - fx)
         + g11 * fy * fx;
}

__global__ void __launch_bounds__(512) mask_kernel(const float* __restrict__ attn,
                                                   const int* __restrict__ pos,
                                                   float* __restrict__ mask_out) {
    const int i   = blockIdx.x;
    const int tid = threadIdx.x;

    __shared__ float m14[196];
    __shared__ float cm[2][196];
    __shared__ float a7[2][49];
    __shared__ int   keep[2][49];
    __shared__ float t_w[2][2][14];
    __shared__ float t_f0[2][2][14];
    __shared__ float t_f1[2][2][14];
    __shared__ int   t_i00[2][2][14];
    __shared__ int   t_i01[2][2][14];
    __shared__ int   t_i10[2][2][14];
    __shared__ int   t_i11[2][2][14];

    if (tid < 196) m14[tid] = attn[i * 196 + tid];

    if (tid >= 448 && tid < 504) {
        const int s    = tid - 448;
        const int pbox = s / 28;
        const int rem  = s - pbox * 28;
        const int axis = rem / 14;
        const int idx  = rem - axis * 14;

        const int* p = pos + i * 12;
        const int oT = p[pbox * 4 + 0];
        const int oL = p[pbox * 4 + 1];
        const int oHi = p[pbox * 4 + 2];
        const int oWi = p[pbox * 4 + 3];
        const int e0 = p[8], e1 = p[9], e2 = p[10], e3 = p[11];

        const float dimO = axis ? (float)oWi : (float)oHi;
        const float off  = axis ? (float)(oL - e1) : (float)(oT - e0);
        const float dimE = axis ? (float)e3 : (float)e2;

        float ty = fmaxf(((float)idx + 0.5f) * dimO / 14.0f - 0.5f, 0.0f);
        float y0 = floorf(ty);
        float y1 = fminf(y0 + 1.0f, dimO - 1.0f);
        t_w[pbox][axis][idx] = ty - y0;
        float Y0 = off + y0;
        float Y1 = off + y1;

        {
            float sy  = fmaxf((Y0 + 0.5f) * 14.0f / dimE - 0.5f, 0.0f);
            float r0f = floorf(sy);
            int r0 = (int)r0f;
            int r1 = min(r0 + 1, 13);
            t_f0[pbox][axis][idx]  = sy - r0f;
            t_i00[pbox][axis][idx] = r0;
            t_i01[pbox][axis][idx] = r1;
        }
        {
            float sy  = fmaxf((Y1 + 0.5f) * 14.0f / dimE - 0.5f, 0.0f);
            float r0f = floorf(sy);
            int r0 = (int)r0f;
            int r1 = min(r0 + 1, 13);
            t_f1[pbox][axis][idx]  = sy - r0f;
            t_i10[pbox][axis][idx] = r0;
            t_i11[pbox][axis][idx] = r1;
        }
    }
    __syncthreads();

    const int box = tid >> 8;
    const int t   = tid & 255;

    if (t < 196) {
        const int y = t / 14;
        const int x = t % 14;

        float wy  = t_w[box][0][y];
        float wx  = t_w[box][1][x];
        float fyA = t_f0[box][0][y], fyB = t_f1[box][0][y];
        float fxA = t_f0[box][1][x], fxB = t_f1[box][1][x];
        int rA0 = t_i00[box][0][y], rA1 = t_i01[box][0][y];
        int rB0 = t_i10[box][0][y], rB1 = t_i11[box][0][y];
        int cA0 = t_i00[box][1][x], cA1 = t_i01[box][1][x];
        int cB0 = t_i10[box][1][x], cB1 = t_i11[box][1][x];

        float v00 = bilin_combine(m14, rA0, rA1, cA0, cA1, fyA, fxA);
        float v01 = bilin_combine(m14, rA0, rA1, cB0, cB1, fyA, fxB);
        float v10 = bilin_combine(m14, rB0, rB1, cA0, cA1, fyB, fxA);
        float v11 = bilin_combine(m14, rB0, rB1, cB0, cB1, fyB, fxB);

        cm[box][t] = v00 * (1.0f - wy) * (1.0f - wx)
                   + v01 * (1.0f - wy) * wx
                   + v10 * wy * (1.0f - wx)
                   + v11 * wy * wx;
    }
    __syncthreads();

    if (t < 49) {
        const int qy = t / 7;
        const int qx = t % 7;
        const float* c = cm[box];
        float s = (c[(2 * qy) * 14 + 2 * qx] + c[(2 * qy) * 14 + 2 * qx + 1]
                 + c[(2 * qy + 1) * 14 + 2 * qx] + c[(2 * qy + 1) * 14 + 2 * qx + 1]) * 0.25f;
        a7[box][t] = s;
    }
    __syncthreads();

    if (t < 49) {
        const float v = a7[box][t];
        int rank = 0;
        #pragma unroll
        for (int j = 0; j < 49; ++j) {
            float u = a7[box][j];
            rank += (u > v) || (u == v && j < t);
        }
        keep[box][t] = (rank < 25);
    }
    __syncthreads();

    if (t < 196) {
        const int y = t / 14;
        const int x = t % 14;
        const int q = (y >> 1) * 7 + (x >> 1);
        mask_out[(box * BS_N + i) * 196 + t] = keep[box][q] ? 0.0f : 1.0f;
    }
}

// ---------------------------------------------------------------------------
// Launch: fork-join so mask runs concurrently with split+GEMM.
// Stream/events are created fresh each call (deterministic) and intentionally
// not destroyed: destroying a forked stream before capture ends would
// invalidate the capture. kernel_launch is called only a handful of times
// (correctness + capture); the timed path replays the captured graph, whose
// two branches execute in parallel.
// ---------------------------------------------------------------------------
extern "C" void kernel_launch(void* const* d_in, const int* in_sizes, int n_in,
                              void* d_out, int out_size) {
    const float* attn        = (const float*)d_in[0];   // [8192, 196]
    const int*   pos         = (const int*)d_in[1];     // [8192, 3, 4]
    const float* image_embed = (const float*)d_in[2];   // [16384, 768]
    const float* Wm          = (const float*)d_in[3];   // [400, 768]
    const float* bias        = (const float*)d_in[4];   // [400]

    float* logits = (float*)d_out;                      // [16384, 400]
    float* mask   = (float*)d_out + LOGITS_ELEMS;       // [16384, 196]

    cudaFuncSetAttribute(gemm_hmma_kernel,
                         cudaFuncAttributeMaxDynamicSharedMemorySize,
                         SMEM_GEMM_TOTAL);

    // Try to fork a side branch for the (independent) mask kernel.
    cudaStream_t s2 = nullptr;
    cudaEvent_t  e1 = nullptr, e2 = nullptr;
    bool forked =
        (cudaStreamCreateWithFlags(&s2, cudaStreamNonBlocking) == cudaSuccess) &&
        (cudaEventCreateWithFlags(&e1, cudaEventDisableTiming) == cudaSuccess) &&
        (cudaEventCreateWithFlags(&e2, cudaEventDisableTiming) == cudaSuccess);

    if (forked) {
        forked = (cudaEventRecord(e1, (cudaStream_t)0) == cudaSuccess) &&
                 (cudaStreamWaitEvent(s2, e1, 0) == cudaSuccess);
    }

    if (forked) {
        mask_kernel<<<BS_N, 512, 0, s2>>>(attn, pos, mask);
        cudaEventRecord(e2, s2);
    }

    // Main branch: splits feed the GEMM.
    {
        int nA = M_TOTAL * DIM;
        split_kernel<<<(nA / 8 + 255) / 256, 256>>>(image_embed, nA, 0);
        int nW = NUM_CLASSES * DIM;
        split_kernel<<<(nW / 8 + 255) / 256, 256>>>(Wm, nW, 1);
    }
    dim3 ggrid(NUM_CLASSES / BN, M_TOTAL / BM);
    gemm_hmma_kernel<<<ggrid, 256, SMEM_GEMM_TOTAL>>>(bias, logits);

    if (forked) {
        // Join: downstream harness work depends on the mask branch too.
        cudaStreamWaitEvent((cudaStream_t)0, e2, 0);
    } else {
        // Fallback: proven serial path.
        mask_kernel<<<BS_N, 512>>>(attn, pos, mask);
    }
}

// round 7
// speedup vs baseline: 2.5205x; 1.2287x over previous
#include <cuda_runtime.h>
#include <cuda_bf16.h>
#include <cstdint>

// ---------------------------------------------------------------------------
// Problem constants
// ---------------------------------------------------------------------------
#define BS_N        8192
#define NUM_CLASSES 400
#define DIM         768
#define M_TOTAL     (2 * BS_N)          // 16384 rows
#define LOGITS_ELEMS (M_TOTAL * NUM_CLASSES)

// ---------------------------------------------------------------------------
// Scratch: bf16 hi/lo splits of A (image_embed) and W
// ---------------------------------------------------------------------------
__device__ __nv_bfloat16 g_Ahi[(size_t)M_TOTAL * DIM];
__device__ __nv_bfloat16 g_Alo[(size_t)M_TOTAL * DIM];
__device__ __nv_bfloat16 g_Whi[(size_t)NUM_CLASSES * DIM];
__device__ __nv_bfloat16 g_Wlo[(size_t)NUM_CLASSES * DIM];

// ---------------------------------------------------------------------------
// Split kernel: fp32 -> (bf16 hi, bf16 lo), 8 elems / thread, 16B stores
// ---------------------------------------------------------------------------
__global__ void __launch_bounds__(256) split_kernel(const float* __restrict__ in,
                                                    int n, int which) {
    int i8 = (blockIdx.x * 256 + threadIdx.x) * 8;
    if (i8 >= n) return;
    __nv_bfloat16* hi = which ? g_Whi : g_Ahi;
    __nv_bfloat16* lo = which ? g_Wlo : g_Alo;

    float4 v0 = *reinterpret_cast<const float4*>(in + i8);
    float4 v1 = *reinterpret_cast<const float4*>(in + i8 + 4);

    float f[8] = {v0.x, v0.y, v0.z, v0.w, v1.x, v1.y, v1.z, v1.w};
    __nv_bfloat16 h[8], l[8];
    #pragma unroll
    for (int j = 0; j < 8; ++j) {
        h[j] = __float2bfloat16(f[j]);
        l[j] = __float2bfloat16(f[j] - __bfloat162float(h[j]));
    }
    *reinterpret_cast<uint4*>(hi + i8) = *reinterpret_cast<const uint4*>(h);
    *reinterpret_cast<uint4*>(lo + i8) = *reinterpret_cast<const uint4*>(l);
}

// ---------------------------------------------------------------------------
// HMMA GEMM: C[16384,400] = A @ W^T + b   (3-term bf16 split, fp32 accum)
// CTA 128x80x64, 8 warps (4m x 2n). SW128-swizzled SMEM (128B rows),
// ldmatrix fragment loads, double-buffered cp.async stages.
// ---------------------------------------------------------------------------
#define BM 128
#define BN 80
#define BK 64
#define NCHUNKS (DIM / BK)                // 12

// per-stage byte offsets (each tile: rows x 128 bytes)
#define SA_H 0
#define SA_L (SA_H + BM * 128)            // 16384
#define SB_H (SA_L + BM * 128)            // 32768
#define SB_L (SB_H + BN * 128)            // 43008
#define STAGE_B (SB_L + BN * 128)         // 53248
#define SMEM_GEMM_TOTAL (2 * STAGE_B)     // 106496

__device__ __forceinline__ uint32_t smem_u32(const void* p) {
    uint32_t a;
    asm("{ .reg .u64 t; cvta.to.shared.u64 t, %1; cvt.u32.u64 %0, t; }"
        : "=r"(a) : "l"(p));
    return a;
}

__device__ __forceinline__ void cp_async16(uint32_t s, const void* g) {
    asm volatile("cp.async.cg.shared.global [%0], [%1], 16;" :: "r"(s), "l"(g));
}

__device__ __forceinline__ void cp_commit() {
    asm volatile("cp.async.commit_group;" ::: "memory");
}

template <int N>
__device__ __forceinline__ void cp_wait() {
    asm volatile("cp.async.wait_group %0;" :: "n"(N) : "memory");
}

__device__ __forceinline__ void ldsm_x4(uint32_t& r0, uint32_t& r1,
                                        uint32_t& r2, uint32_t& r3, uint32_t a) {
    asm volatile("ldmatrix.sync.aligned.m8n8.x4.shared.b16 {%0,%1,%2,%3}, [%4];"
                 : "=r"(r0), "=r"(r1), "=r"(r2), "=r"(r3) : "r"(a));
}

__device__ __forceinline__ void ldsm_x2(uint32_t& r0, uint32_t& r1, uint32_t a) {
    asm volatile("ldmatrix.sync.aligned.m8n8.x2.shared.b16 {%0,%1}, [%2];"
                 : "=r"(r0), "=r"(r1) : "r"(a));
}

__device__ __forceinline__ void mma16816(float* c, uint32_t a0, uint32_t a1,
                                         uint32_t a2, uint32_t a3,
                                         uint32_t b0, uint32_t b1) {
    asm volatile(
        "mma.sync.aligned.m16n8k16.row.col.f32.bf16.bf16.f32 "
        "{%0,%1,%2,%3}, {%4,%5,%6,%7}, {%8,%9}, {%0,%1,%2,%3};"
        : "+f"(c[0]), "+f"(c[1]), "+f"(c[2]), "+f"(c[3])
        : "r"(a0), "r"(a1), "r"(a2), "r"(a3), "r"(b0), "r"(b1));
}

// Load one k-chunk (BK=64) of all four tiles into a stage, SW128-swizzled.
__device__ __forceinline__ void load_stage(uint32_t sbase,
                                           const __nv_bfloat16* Ah,
                                           const __nv_bfloat16* Al,
                                           const __nv_bfloat16* Bh,
                                           const __nv_bfloat16* Bl,
                                           int k0, int tid) {
    // A: 128 rows x 8 segs of 16B (= 64 bf16) -> 1024 chunks, 4 per thread
    #pragma unroll
    for (int j = 0; j < 4; ++j) {
        int idx = tid + j * 256;
        int row = idx >> 3;
        int seg = idx & 7;
        size_t goff = (size_t)row * DIM + k0 + seg * 8;
        uint32_t sw = (uint32_t)row * 128 + (uint32_t)((seg ^ (row & 7)) << 4);
        cp_async16(sbase + SA_H + sw, Ah + goff);
        cp_async16(sbase + SA_L + sw, Al + goff);
    }
    // B: 80 rows x 8 segs -> 640 chunks
    #pragma unroll
    for (int j = 0; j < 2; ++j) {
        int idx = tid + j * 256;
        int row = idx >> 3;
        int seg = idx & 7;
        size_t goff = (size_t)row * DIM + k0 + seg * 8;
        uint32_t sw = (uint32_t)row * 128 + (uint32_t)((seg ^ (row & 7)) << 4);
        cp_async16(sbase + SB_H + sw, Bh + goff);
        cp_async16(sbase + SB_L + sw, Bl + goff);
    }
    if (tid < 128) {
        int idx = 512 + tid;
        int row = idx >> 3;
        int seg = idx & 7;
        size_t goff = (size_t)row * DIM + k0 + seg * 8;
        uint32_t sw = (uint32_t)row * 128 + (uint32_t)((seg ^ (row & 7)) << 4);
        cp_async16(sbase + SB_H + sw, Bh + goff);
        cp_async16(sbase + SB_L + sw, Bl + goff);
    }
    cp_commit();
}

__global__ void __launch_bounds__(256, 2) gemm_hmma_kernel(const float* __restrict__ bias,
                                                           float* __restrict__ C) {
    extern __shared__ char smem[];
    const int tid    = threadIdx.x;
    const int warp   = tid >> 5;
    const int lane   = tid & 31;
    const int warp_m = warp >> 1;
    const int warp_n = warp & 1;
    const uint32_t sb = smem_u32(smem);

    const int m0 = blockIdx.y * BM;
    const int n0 = blockIdx.x * BN;

    const __nv_bfloat16* Ah = g_Ahi + (size_t)m0 * DIM;
    const __nv_bfloat16* Al = g_Alo + (size_t)m0 * DIM;
    const __nv_bfloat16* Bh = g_Whi + (size_t)n0 * DIM;
    const __nv_bfloat16* Bl = g_Wlo + (size_t)n0 * DIM;

    float acc[2][5][4];
    #pragma unroll
    for (int mt = 0; mt < 2; ++mt)
        #pragma unroll
        for (int nt = 0; nt < 5; ++nt)
            #pragma unroll
            for (int j = 0; j < 4; ++j)
                acc[mt][nt][j] = 0.0f;

    // ldmatrix per-lane decomposition
    const int lmat = lane >> 3;            // matrix id 0..3
    const int li   = lane & 7;             // row-within-matrix
    // A x4: mats (m0k0, m8k0, m0k8, m8k8): row = rb + (mat&1)*8 + li, shalf = mat>>1
    const int a_rlo   = (lmat & 1) << 3;
    const int a_shalf = lmat >> 1;
    // row byte-offsets (per mt)
    uint32_t a_row[2];
    #pragma unroll
    for (int mt = 0; mt < 2; ++mt)
        a_row[mt] = (uint32_t)(warp_m * 32 + mt * 16 + a_rlo + li) * 128;
    // B x4 pair p: mats (nt0 k0, nt0 k8, nt0+1 k0, nt0+1 k8):
    //   row = nb + (p*2 + (mat>>1))*8 + li, shalf = mat&1
    const int b_shalf = lmat & 1;
    uint32_t b_row[2];
    #pragma unroll
    for (int p = 0; p < 2; ++p)
        b_row[p] = (uint32_t)(warp_n * 40 + (p * 2 + (lmat >> 1)) * 8 + li) * 128;
    // B x2 (tile 4): lanes 0-15, mat 0/1 -> k0/k8
    const int b2_shalf = lmat & 1;
    const uint32_t b2_row = (uint32_t)(warp_n * 40 + 32 + li) * 128;

    load_stage(sb, Ah, Al, Bh, Bl, 0, tid);

    for (int c = 0; c < NCHUNKS; ++c) {
        const uint32_t cur = sb + (uint32_t)(c & 1) * STAGE_B;
        if (c + 1 < NCHUNKS) {
            load_stage(sb + (uint32_t)((c + 1) & 1) * STAGE_B, Ah, Al, Bh, Bl,
                       (c + 1) * BK, tid);
            cp_wait<1>();
        } else {
            cp_wait<0>();
        }
        __syncthreads();

        #pragma unroll
        for (int k16 = 0; k16 < 4; ++k16) {
            const int s2 = k16 * 2;
            // A fragments
            uint32_t ah[2][4], al[2][4];
            #pragma unroll
            for (int mt = 0; mt < 2; ++mt) {
                uint32_t axor = (uint32_t)((((s2 + a_shalf) ^ li) & 7) << 4);
                ldsm_x4(ah[mt][0], ah[mt][1], ah[mt][2], ah[mt][3],
                        cur + SA_H + a_row[mt] + axor);
                ldsm_x4(al[mt][0], al[mt][1], al[mt][2], al[mt][3],
                        cur + SA_L + a_row[mt] + axor);
            }
            // B fragments: tiles 0..3 via two x4, tile 4 via x2 (hi & lo)
            uint32_t bh[5][2], bl[5][2];
            {
                uint32_t bxor = (uint32_t)((((s2 + b_shalf) ^ li) & 7) << 4);
                #pragma unroll
                for (int p = 0; p < 2; ++p) {
                    ldsm_x4(bh[p * 2][0], bh[p * 2][1], bh[p * 2 + 1][0], bh[p * 2 + 1][1],
                            cur + SB_H + b_row[p] + bxor);
                    ldsm_x4(bl[p * 2][0], bl[p * 2][1], bl[p * 2 + 1][0], bl[p * 2 + 1][1],
                            cur + SB_L + b_row[p] + bxor);
                }
                uint32_t b2xor = (uint32_t)((((s2 + b2_shalf) ^ li) & 7) << 4);
                ldsm_x2(bh[4][0], bh[4][1], cur + SB_H + b2_row + b2xor);
                ldsm_x2(bl[4][0], bl[4][1], cur + SB_L + b2_row + b2xor);
            }
            // 3-term MMAs
            #pragma unroll
            for (int mt = 0; mt < 2; ++mt)
                #pragma unroll
                for (int nt = 0; nt < 5; ++nt) {
                    mma16816(acc[mt][nt], ah[mt][0], ah[mt][1], ah[mt][2], ah[mt][3],
                             bh[nt][0], bh[nt][1]);
                    mma16816(acc[mt][nt], ah[mt][0], ah[mt][1], ah[mt][2], ah[mt][3],
                             bl[nt][0], bl[nt][1]);
                    mma16816(acc[mt][nt], al[mt][0], al[mt][1], al[mt][2], al[mt][3],
                             bh[nt][0], bh[nt][1]);
                }
        }
        __syncthreads();
    }

    // Epilogue
    const int fr = lane >> 2;
    const int fc = (lane & 3) * 2;
    #pragma unroll
    for (int mt = 0; mt < 2; ++mt) {
        int row = m0 + warp_m * 32 + mt * 16 + fr;
        #pragma unroll
        for (int nt = 0; nt < 5; ++nt) {
            int col = n0 + warp_n * 40 + nt * 8 + fc;
            float b0 = __ldg(bias + col);
            float b1 = __ldg(bias + col + 1);
            float2 v0 = make_float2(acc[mt][nt][0] + b0, acc[mt][nt][1] + b1);
            float2 v1 = make_float2(acc[mt][nt][2] + b0, acc[mt][nt][3] + b1);
            *reinterpret_cast<float2*>(&C[(size_t)row * NUM_CLASSES + col]) = v0;
            *reinterpret_cast<float2*>(&C[(size_t)(row + 8) * NUM_CLASSES + col]) = v1;
        }
    }
}

// ---------------------------------------------------------------------------
// Mask kernel (UNCHANGED — bit-exact verified at rel_err 5.112523e-06)
// ---------------------------------------------------------------------------
__device__ __forceinline__ float bilin_combine(const float* __restrict__ m,
                                               int r0, int r1, int c0, int c1,
                                               float fy, float fx) {
    float g00 = m[r0 * 14 + c0];
    float g01 = m[r0 * 14 + c1];
    float g10 = m[r1 * 14 + c0];
    float g11 = m[r1 * 14 + c1];
    return g00 * (1.0f - fy) * (1.0f - fx)
         + g01 * (1.0f - fy) * fx
         + g10 * fy * (1.0f - fx)
         + g11 * fy * fx;
}

__global__ void __launch_bounds__(512) mask_kernel(const float* __restrict__ attn,
                                                   const int* __restrict__ pos,
                                                   float* __restrict__ mask_out) {
    const int i   = blockIdx.x;
    const int tid = threadIdx.x;

    __shared__ float m14[196];
    __shared__ float cm[2][196];
    __shared__ float a7[2][49];
    __shared__ int   keep[2][49];
    __shared__ float t_w[2][2][14];
    __shared__ float t_f0[2][2][14];
    __shared__ float t_f1[2][2][14];
    __shared__ int   t_i00[2][2][14];
    __shared__ int   t_i01[2][2][14];
    __shared__ int   t_i10[2][2][14];
    __shared__ int   t_i11[2][2][14];

    if (tid < 196) m14[tid] = attn[i * 196 + tid];

    if (tid >= 448 && tid < 504) {
        const int s    = tid - 448;
        const int pbox = s / 28;
        const int rem  = s - pbox * 28;
        const int axis = rem / 14;
        const int idx  = rem - axis * 14;

        const int* p = pos + i * 12;
        const int oT = p[pbox * 4 + 0];
        const int oL = p[pbox * 4 + 1];
        const int oHi = p[pbox * 4 + 2];
        const int oWi = p[pbox * 4 + 3];
        const int e0 = p[8], e1 = p[9], e2 = p[10], e3 = p[11];

        const float dimO = axis ? (float)oWi : (float)oHi;
        const float off  = axis ? (float)(oL - e1) : (float)(oT - e0);
        const float dimE = axis ? (float)e3 : (float)e2;

        float ty = fmaxf(((float)idx + 0.5f) * dimO / 14.0f - 0.5f, 0.0f);
        float y0 = floorf(ty);
        float y1 = fminf(y0 + 1.0f, dimO - 1.0f);
        t_w[pbox][axis][idx] = ty - y0;
        float Y0 = off + y0;
        float Y1 = off + y1;

        {
            float sy  = fmaxf((Y0 + 0.5f) * 14.0f / dimE - 0.5f, 0.0f);
            float r0f = floorf(sy);
            int r0 = (int)r0f;
            int r1 = min(r0 + 1, 13);
            t_f0[pbox][axis][idx]  = sy - r0f;
            t_i00[pbox][axis][idx] = r0;
            t_i01[pbox][axis][idx] = r1;
        }
        {
            float sy  = fmaxf((Y1 + 0.5f) * 14.0f / dimE - 0.5f, 0.0f);
            float r0f = floorf(sy);
            int r0 = (int)r0f;
            int r1 = min(r0 + 1, 13);
            t_f1[pbox][axis][idx]  = sy - r0f;
            t_i10[pbox][axis][idx] = r0;
            t_i11[pbox][axis][idx] = r1;
        }
    }
    __syncthreads();

    const int box = tid >> 8;
    const int t   = tid & 255;

    if (t < 196) {
        const int y = t / 14;
        const int x = t % 14;

        float wy  = t_w[box][0][y];
        float wx  = t_w[box][1][x];
        float fyA = t_f0[box][0][y], fyB = t_f1[box][0][y];
        float fxA = t_f0[box][1][x], fxB = t_f1[box][1][x];
        int rA0 = t_i00[box][0][y], rA1 = t_i01[box][0][y];
        int rB0 = t_i10[box][0][y], rB1 = t_i11[box][0][y];
        int cA0 = t_i00[box][1][x], cA1 = t_i01[box][1][x];
        int cB0 = t_i10[box][1][x], cB1 = t_i11[box][1][x];

        float v00 = bilin_combine(m14, rA0, rA1, cA0, cA1, fyA, fxA);
        float v01 = bilin_combine(m14, rA0, rA1, cB0, cB1, fyA, fxB);
        float v10 = bilin_combine(m14, rB0, rB1, cA0, cA1, fyB, fxA);
        float v11 = bilin_combine(m14, rB0, rB1, cB0, cB1, fyB, fxB);

        cm[box][t] = v00 * (1.0f - wy) * (1.0f - wx)
                   + v01 * (1.0f - wy) * wx
                   + v10 * wy * (1.0f - wx)
                   + v11 * wy * wx;
    }
    __syncthreads();

    if (t < 49) {
        const int qy = t / 7;
        const int qx = t % 7;
        const float* c = cm[box];
        float s = (c[(2 * qy) * 14 + 2 * qx] + c[(2 * qy) * 14 + 2 * qx + 1]
                 + c[(2 * qy + 1) * 14 + 2 * qx] + c[(2 * qy + 1) * 14 + 2 * qx + 1]) * 0.25f;
        a7[box][t] = s;
    }
    __syncthreads();

    if (t < 49) {
        const float v = a7[box][t];
        int rank = 0;
        #pragma unroll
        for (int j = 0; j < 49; ++j) {
            float u = a7[box][j];
            rank += (u > v) || (u == v && j < t);
        }
        keep[box][t] = (rank < 25);
    }
    __syncthreads();

    if (t < 196) {
        const int y = t / 14;
        const int x = t % 14;
        const int q = (y >> 1) * 7 + (x >> 1);
        mask_out[(box * BS_N + i) * 196 + t] = keep[box][q] ? 0.0f : 1.0f;
    }
}

// ---------------------------------------------------------------------------
// Launch: fork-join so mask runs concurrently with split+GEMM.
// ---------------------------------------------------------------------------
extern "C" void kernel_launch(void* const* d_in, const int* in_sizes, int n_in,
                              void* d_out, int out_size) {
    const float* attn        = (const float*)d_in[0];   // [8192, 196]
    const int*   pos         = (const int*)d_in[1];     // [8192, 3, 4]
    const float* image_embed = (const float*)d_in[2];   // [16384, 768]
    const float* Wm          = (const float*)d_in[3];   // [400, 768]
    const float* bias        = (const float*)d_in[4];   // [400]

    float* logits = (float*)d_out;                      // [16384, 400]
    float* mask   = (float*)d_out + LOGITS_ELEMS;       // [16384, 196]

    cudaFuncSetAttribute(gemm_hmma_kernel,
                         cudaFuncAttributeMaxDynamicSharedMemorySize,
                         SMEM_GEMM_TOTAL);

    cudaStream_t s2 = nullptr;
    cudaEvent_t  e1 = nullptr, e2 = nullptr;
    bool forked =
        (cudaStreamCreateWithFlags(&s2, cudaStreamNonBlocking) == cudaSuccess) &&
        (cudaEventCreateWithFlags(&e1, cudaEventDisableTiming) == cudaSuccess) &&
        (cudaEventCreateWithFlags(&e2, cudaEventDisableTiming) == cudaSuccess);

    if (forked) {
        forked = (cudaEventRecord(e1, (cudaStream_t)0) == cudaSuccess) &&
                 (cudaStreamWaitEvent(s2, e1, 0) == cudaSuccess);
    }

    if (forked) {
        mask_kernel<<<BS_N, 512, 0, s2>>>(attn, pos, mask);
        cudaEventRecord(e2, s2);
    }

    {
        int nA = M_TOTAL * DIM;
        split_kernel<<<(nA / 8 + 255) / 256, 256>>>(image_embed, nA, 0);
        int nW = NUM_CLASSES * DIM;
        split_kernel<<<(nW / 8 + 255) / 256, 256>>>(Wm, nW, 1);
    }
    dim3 ggrid(NUM_CLASSES / BN, M_TOTAL / BM);
    gemm_hmma_kernel<<<ggrid, 256, SMEM_GEMM_TOTAL>>>(bias, logits);

    if (forked) {
        cudaStreamWaitEvent((cudaStream_t)0, e2, 0);
    } else {
        mask_kernel<<<BS_N, 512>>>(attn, pos, mask);
    }
}

// round 8
// speedup vs baseline: 2.6432x; 1.0487x over previous
#include <cuda_runtime.h>
#include <cuda_bf16.h>
#include <cstdint>

// ---------------------------------------------------------------------------
// Problem constants
// ---------------------------------------------------------------------------
#define BS_N        8192
#define NUM_CLASSES 400
#define DIM         768
#define M_TOTAL     (2 * BS_N)          // 16384 rows
#define LOGITS_ELEMS (M_TOTAL * NUM_CLASSES)

// ---------------------------------------------------------------------------
// Scratch: bf16 hi/lo splits of A (image_embed) and W
// ---------------------------------------------------------------------------
__device__ __nv_bfloat16 g_Ahi[(size_t)M_TOTAL * DIM];
__device__ __nv_bfloat16 g_Alo[(size_t)M_TOTAL * DIM];
__device__ __nv_bfloat16 g_Whi[(size_t)NUM_CLASSES * DIM];
__device__ __nv_bfloat16 g_Wlo[(size_t)NUM_CLASSES * DIM];

#define NA_ELEMS (M_TOTAL * DIM)        // 12,582,912 (divisible by 8)
#define NW_ELEMS (NUM_CLASSES * DIM)    // 307,200   (divisible by 8)
#define SPLIT_GROUPS ((NA_ELEMS + NW_ELEMS) / 8)

// ---------------------------------------------------------------------------
// Fused split kernel: A then W regions, fp32 -> (bf16 hi, bf16 lo)
// ---------------------------------------------------------------------------
__global__ void __launch_bounds__(256) split_kernel(const float* __restrict__ inA,
                                                    const float* __restrict__ inW) {
    int g = blockIdx.x * 256 + threadIdx.x;
    if (g >= SPLIT_GROUPS) return;

    const float* in;
    __nv_bfloat16 *hi, *lo;
    int i8;
    if (g < NA_ELEMS / 8) {
        in = inA; hi = g_Ahi; lo = g_Alo; i8 = g * 8;
    } else {
        in = inW; hi = g_Whi; lo = g_Wlo; i8 = (g - NA_ELEMS / 8) * 8;
    }

    float4 v0 = *reinterpret_cast<const float4*>(in + i8);
    float4 v1 = *reinterpret_cast<const float4*>(in + i8 + 4);

    float f[8] = {v0.x, v0.y, v0.z, v0.w, v1.x, v1.y, v1.z, v1.w};
    __nv_bfloat16 h[8], l[8];
    #pragma unroll
    for (int j = 0; j < 8; ++j) {
        h[j] = __float2bfloat16(f[j]);
        l[j] = __float2bfloat16(f[j] - __bfloat162float(h[j]));
    }
    *reinterpret_cast<uint4*>(hi + i8) = *reinterpret_cast<const uint4*>(h);
    *reinterpret_cast<uint4*>(lo + i8) = *reinterpret_cast<const uint4*>(l);
}

// ---------------------------------------------------------------------------
// HMMA GEMM: C[16384,400] = A @ W^T + b   (3-term bf16 split, fp32 accum)
// CTA 128x80x64, 8 warps (4m x 2n). SW128-swizzled SMEM, ldmatrix loads,
// double-buffered cp.async stages + double-buffered register fragments.
// ---------------------------------------------------------------------------
#define BM 128
#define BN 80
#define BK 64
#define NCHUNKS (DIM / BK)                // 12

#define SA_H 0
#define SA_L (SA_H + BM * 128)            // 16384
#define SB_H (SA_L + BM * 128)            // 32768
#define SB_L (SB_H + BN * 128)            // 43008
#define STAGE_B (SB_L + BN * 128)         // 53248
#define SMEM_GEMM_TOTAL (2 * STAGE_B)     // 106496

__device__ __forceinline__ uint32_t smem_u32(const void* p) {
    uint32_t a;
    asm("{ .reg .u64 t; cvta.to.shared.u64 t, %1; cvt.u32.u64 %0, t; }"
        : "=r"(a) : "l"(p));
    return a;
}

__device__ __forceinline__ void cp_async16(uint32_t s, const void* g) {
    asm volatile("cp.async.cg.shared.global [%0], [%1], 16;" :: "r"(s), "l"(g));
}

__device__ __forceinline__ void cp_commit() {
    asm volatile("cp.async.commit_group;" ::: "memory");
}

template <int N>
__device__ __forceinline__ void cp_wait() {
    asm volatile("cp.async.wait_group %0;" :: "n"(N) : "memory");
}

__device__ __forceinline__ void ldsm_x4(uint32_t& r0, uint32_t& r1,
                                        uint32_t& r2, uint32_t& r3, uint32_t a) {
    asm volatile("ldmatrix.sync.aligned.m8n8.x4.shared.b16 {%0,%1,%2,%3}, [%4];"
                 : "=r"(r0), "=r"(r1), "=r"(r2), "=r"(r3) : "r"(a));
}

__device__ __forceinline__ void ldsm_x2(uint32_t& r0, uint32_t& r1, uint32_t a) {
    asm volatile("ldmatrix.sync.aligned.m8n8.x2.shared.b16 {%0,%1}, [%2];"
                 : "=r"(r0), "=r"(r1) : "r"(a));
}

__device__ __forceinline__ void mma16816(float* c, uint32_t a0, uint32_t a1,
                                         uint32_t a2, uint32_t a3,
                                         uint32_t b0, uint32_t b1) {
    asm volatile(
        "mma.sync.aligned.m16n8k16.row.col.f32.bf16.bf16.f32 "
        "{%0,%1,%2,%3}, {%4,%5,%6,%7}, {%8,%9}, {%0,%1,%2,%3};"
        : "+f"(c[0]), "+f"(c[1]), "+f"(c[2]), "+f"(c[3])
        : "r"(a0), "r"(a1), "r"(a2), "r"(a3), "r"(b0), "r"(b1));
}

struct Frags {
    uint32_t ah[2][4], al[2][4];
    uint32_t bh[5][2], bl[5][2];
};

__device__ __forceinline__ void load_stage(uint32_t sbase,
                                           const __nv_bfloat16* Ah,
                                           const __nv_bfloat16* Al,
                                           const __nv_bfloat16* Bh,
                                           const __nv_bfloat16* Bl,
                                           int k0, int tid) {
    #pragma unroll
    for (int j = 0; j < 4; ++j) {
        int idx = tid + j * 256;
        int row = idx >> 3;
        int seg = idx & 7;
        size_t goff = (size_t)row * DIM + k0 + seg * 8;
        uint32_t sw = (uint32_t)row * 128 + (uint32_t)((seg ^ (row & 7)) << 4);
        cp_async16(sbase + SA_H + sw, Ah + goff);
        cp_async16(sbase + SA_L + sw, Al + goff);
    }
    #pragma unroll
    for (int j = 0; j < 2; ++j) {
        int idx = tid + j * 256;
        int row = idx >> 3;
        int seg = idx & 7;
        size_t goff = (size_t)row * DIM + k0 + seg * 8;
        uint32_t sw = (uint32_t)row * 128 + (uint32_t)((seg ^ (row & 7)) << 4);
        cp_async16(sbase + SB_H + sw, Bh + goff);
        cp_async16(sbase + SB_L + sw, Bl + goff);
    }
    if (tid < 128) {
        int idx = 512 + tid;
        int row = idx >> 3;
        int seg = idx & 7;
        size_t goff = (size_t)row * DIM + k0 + seg * 8;
        uint32_t sw = (uint32_t)row * 128 + (uint32_t)((seg ^ (row & 7)) << 4);
        cp_async16(sbase + SB_H + sw, Bh + goff);
        cp_async16(sbase + SB_L + sw, Bl + goff);
    }
    cp_commit();
}

__global__ void __launch_bounds__(256, 2) gemm_hmma_kernel(const float* __restrict__ bias,
                                                           float* __restrict__ C) {
    extern __shared__ char smem[];
    const int tid    = threadIdx.x;
    const int warp   = tid >> 5;
    const int lane   = tid & 31;
    const int warp_m = warp >> 1;
    const int warp_n = warp & 1;
    const uint32_t sb = smem_u32(smem);

    const int m0 = blockIdx.y * BM;
    const int n0 = blockIdx.x * BN;

    const __nv_bfloat16* Ah = g_Ahi + (size_t)m0 * DIM;
    const __nv_bfloat16* Al = g_Alo + (size_t)m0 * DIM;
    const __nv_bfloat16* Bh = g_Whi + (size_t)n0 * DIM;
    const __nv_bfloat16* Bl = g_Wlo + (size_t)n0 * DIM;

    float acc[2][5][4];
    #pragma unroll
    for (int mt = 0; mt < 2; ++mt)
        #pragma unroll
        for (int nt = 0; nt < 5; ++nt)
            #pragma unroll
            for (int j = 0; j < 4; ++j)
                acc[mt][nt][j] = 0.0f;

    // ldmatrix per-lane decomposition (see round-7 derivation)
    const int lmat = lane >> 3;
    const int li   = lane & 7;
    const int a_rlo   = (lmat & 1) << 3;
    const int a_shalf = lmat >> 1;
    uint32_t a_row[2];
    #pragma unroll
    for (int mt = 0; mt < 2; ++mt)
        a_row[mt] = (uint32_t)(warp_m * 32 + mt * 16 + a_rlo + li) * 128;
    const int b_shalf = lmat & 1;
    uint32_t b_row[2];
    #pragma unroll
    for (int p = 0; p < 2; ++p)
        b_row[p] = (uint32_t)(warp_n * 40 + (p * 2 + (lmat >> 1)) * 8 + li) * 128;
    const int b2_shalf = lmat & 1;
    const uint32_t b2_row = (uint32_t)(warp_n * 40 + 32 + li) * 128;

    // fragment loader for one k16 step within the current stage
    auto load_frags = [&](uint32_t cur, int k16, Frags& f) {
        const int s2 = k16 * 2;
        uint32_t axor = (uint32_t)((((s2 + a_shalf) ^ li) & 7) << 4);
        #pragma unroll
        for (int mt = 0; mt < 2; ++mt) {
            ldsm_x4(f.ah[mt][0], f.ah[mt][1], f.ah[mt][2], f.ah[mt][3],
                    cur + SA_H + a_row[mt] + axor);
            ldsm_x4(f.al[mt][0], f.al[mt][1], f.al[mt][2], f.al[mt][3],
                    cur + SA_L + a_row[mt] + axor);
        }
        uint32_t bxor = (uint32_t)((((s2 + b_shalf) ^ li) & 7) << 4);
        #pragma unroll
        for (int p = 0; p < 2; ++p) {
            ldsm_x4(f.bh[p * 2][0], f.bh[p * 2][1], f.bh[p * 2 + 1][0], f.bh[p * 2 + 1][1],
                    cur + SB_H + b_row[p] + bxor);
            ldsm_x4(f.bl[p * 2][0], f.bl[p * 2][1], f.bl[p * 2 + 1][0], f.bl[p * 2 + 1][1],
                    cur + SB_L + b_row[p] + bxor);
        }
        uint32_t b2xor = (uint32_t)((((s2 + b2_shalf) ^ li) & 7) << 4);
        ldsm_x2(f.bh[4][0], f.bh[4][1], cur + SB_H + b2_row + b2xor);
        ldsm_x2(f.bl[4][0], f.bl[4][1], cur + SB_L + b2_row + b2xor);
    };

    auto do_mmas = [&](Frags& f) {
        #pragma unroll
        for (int mt = 0; mt < 2; ++mt)
            #pragma unroll
            for (int nt = 0; nt < 5; ++nt) {
                mma16816(acc[mt][nt], f.ah[mt][0], f.ah[mt][1], f.ah[mt][2], f.ah[mt][3],
                         f.bh[nt][0], f.bh[nt][1]);
                mma16816(acc[mt][nt], f.ah[mt][0], f.ah[mt][1], f.ah[mt][2], f.ah[mt][3],
                         f.bl[nt][0], f.bl[nt][1]);
                mma16816(acc[mt][nt], f.al[mt][0], f.al[mt][1], f.al[mt][2], f.al[mt][3],
                         f.bh[nt][0], f.bh[nt][1]);
            }
    };

    load_stage(sb, Ah, Al, Bh, Bl, 0, tid);

    Frags f0, f1;
    for (int c = 0; c < NCHUNKS; ++c) {
        const uint32_t cur = sb + (uint32_t)(c & 1) * STAGE_B;
        if (c + 1 < NCHUNKS) {
            load_stage(sb + (uint32_t)((c + 1) & 1) * STAGE_B, Ah, Al, Bh, Bl,
                       (c + 1) * BK, tid);
            cp_wait<1>();
        } else {
            cp_wait<0>();
        }
        __syncthreads();

        // software-pipelined fragments across the 4 k16 steps
        load_frags(cur, 0, f0);
        load_frags(cur, 1, f1);
        do_mmas(f0);
        load_frags(cur, 2, f0);
        do_mmas(f1);
        load_frags(cur, 3, f1);
        do_mmas(f0);
        do_mmas(f1);

        __syncthreads();
    }

    // Epilogue
    const int fr = lane >> 2;
    const int fc = (lane & 3) * 2;
    #pragma unroll
    for (int mt = 0; mt < 2; ++mt) {
        int row = m0 + warp_m * 32 + mt * 16 + fr;
        #pragma unroll
        for (int nt = 0; nt < 5; ++nt) {
            int col = n0 + warp_n * 40 + nt * 8 + fc;
            float b0 = __ldg(bias + col);
            float b1 = __ldg(bias + col + 1);
            float2 v0 = make_float2(acc[mt][nt][0] + b0, acc[mt][nt][1] + b1);
            float2 v1 = make_float2(acc[mt][nt][2] + b0, acc[mt][nt][3] + b1);
            *reinterpret_cast<float2*>(&C[(size_t)row * NUM_CLASSES + col]) = v0;
            *reinterpret_cast<float2*>(&C[(size_t)(row + 8) * NUM_CLASSES + col]) = v1;
        }
    }
}

// ---------------------------------------------------------------------------
// Mask kernel — 416 threads (box = tid/208). FP expression trees identical to
// the verified bit-exact version; only thread mapping and the rank compare
// (packed u64, provably same decisions) changed.
// ---------------------------------------------------------------------------
__device__ __forceinline__ float bilin_combine(const float* __restrict__ m,
                                               int r0, int r1, int c0, int c1,
                                               float fy, float fx) {
    float g00 = m[r0 * 14 + c0];
    float g01 = m[r0 * 14 + c1];
    float g10 = m[r1 * 14 + c0];
    float g11 = m[r1 * 14 + c1];
    return g00 * (1.0f - fy) * (1.0f - fx)
         + g01 * (1.0f - fy) * fx
         + g10 * fy * (1.0f - fx)
         + g11 * fy * fx;
}

__global__ void __launch_bounds__(416) mask_kernel(const float* __restrict__ attn,
                                                   const int* __restrict__ pos,
                                                   float* __restrict__ mask_out) {
    const int i   = blockIdx.x;
    const int tid = threadIdx.x;

    __shared__ float m14[196];
    __shared__ float cm[2][196];
    __shared__ unsigned long long key[2][49];
    __shared__ int   keep[2][49];
    __shared__ float t_w[2][2][14];
    __shared__ float t_f0[2][2][14];
    __shared__ float t_f1[2][2][14];
    __shared__ int   t_i00[2][2][14];
    __shared__ int   t_i01[2][2][14];
    __shared__ int   t_i10[2][2][14];
    __shared__ int   t_i11[2][2][14];

    if (tid < 196) m14[tid] = attn[i * 196 + tid];

    // Phase A: threads 0..55 build weight/index tables (same FP exprs).
    if (tid < 56) {
        const int s    = tid;
        const int pbox = s / 28;
        const int rem  = s - pbox * 28;
        const int axis = rem / 14;
        const int idx  = rem - axis * 14;

        const int* p = pos + i * 12;
        const int oT = p[pbox * 4 + 0];
        const int oL = p[pbox * 4 + 1];
        const int oHi = p[pbox * 4 + 2];
        const int oWi = p[pbox * 4 + 3];
        const int e0 = p[8], e1 = p[9], e2 = p[10], e3 = p[11];

        const float dimO = axis ? (float)oWi : (float)oHi;
        const float off  = axis ? (float)(oL - e1) : (float)(oT - e0);
        const float dimE = axis ? (float)e3 : (float)e2;

        float ty = fmaxf(((float)idx + 0.5f) * dimO / 14.0f - 0.5f, 0.0f);
        float y0 = floorf(ty);
        float y1 = fminf(y0 + 1.0f, dimO - 1.0f);
        t_w[pbox][axis][idx] = ty - y0;
        float Y0 = off + y0;
        float Y1 = off + y1;

        {
            float sy  = fmaxf((Y0 + 0.5f) * 14.0f / dimE - 0.5f, 0.0f);
            float r0f = floorf(sy);
            int r0 = (int)r0f;
            int r1 = min(r0 + 1, 13);
            t_f0[pbox][axis][idx]  = sy - r0f;
            t_i00[pbox][axis][idx] = r0;
            t_i01[pbox][axis][idx] = r1;
        }
        {
            float sy  = fmaxf((Y1 + 0.5f) * 14.0f / dimE - 0.5f, 0.0f);
            float r0f = floorf(sy);
            int r0 = (int)r0f;
            int r1 = min(r0 + 1, 13);
            t_f1[pbox][axis][idx]  = sy - r0f;
            t_i10[pbox][axis][idx] = r0;
            t_i11[pbox][axis][idx] = r1;
        }
    }
    __syncthreads();

    const int box = tid / 208;
    const int t   = tid - box * 208;

    if (t < 196) {
        const int y = t / 14;
        const int x = t % 14;

        float wy  = t_w[box][0][y];
        float wx  = t_w[box][1][x];
        float fyA = t_f0[box][0][y], fyB = t_f1[box][0][y];
        float fxA = t_f0[box][1][x], fxB = t_f1[box][1][x];
        int rA0 = t_i00[box][0][y], rA1 = t_i01[box][0][y];
        int rB0 = t_i10[box][0][y], rB1 = t_i11[box][0][y];
        int cA0 = t_i00[box][1][x], cA1 = t_i01[box][1][x];
        int cB0 = t_i10[box][1][x], cB1 = t_i11[box][1][x];

        float v00 = bilin_combine(m14, rA0, rA1, cA0, cA1, fyA, fxA);
        float v01 = bilin_combine(m14, rA0, rA1, cB0, cB1, fyA, fxB);
        float v10 = bilin_combine(m14, rB0, rB1, cA0, cA1, fyB, fxA);
        float v11 = bilin_combine(m14, rB0, rB1, cB0, cB1, fyB, fxB);

        cm[box][t] = v00 * (1.0f - wy) * (1.0f - wx)
                   + v01 * (1.0f - wy) * wx
                   + v10 * wy * (1.0f - wx)
                   + v11 * wy * wx;
    }
    __syncthreads();

    if (t < 49) {
        const int qy = t / 7;
        const int qx = t % 7;
        const float* c = cm[box];
        float s = (c[(2 * qy) * 14 + 2 * qx] + c[(2 * qy) * 14 + 2 * qx + 1]
                 + c[(2 * qy + 1) * 14 + 2 * qx] + c[(2 * qy + 1) * 14 + 2 * qx + 1]) * 0.25f;
        // a7 values are >= 0, so float bit pattern is order-isomorphic.
        // key encodes (value, index-preference) so key_j > key_t
        //   <=> (u_j > u_t) || (u_j == u_t && j < t)   — same decision as before.
        key[box][t] = ((unsigned long long)__float_as_uint(s) << 6)
                    | (unsigned long long)(48 - t);
    }
    __syncthreads();

    if (t < 49) {
        const unsigned long long kv = key[box][t];
        int rank = 0;
        #pragma unroll
        for (int j = 0; j < 49; ++j)
            rank += (key[box][j] > kv);
        keep[box][t] = (rank < 25);
    }
    __syncthreads();

    if (t < 196) {
        const int y = t / 14;
        const int x = t % 14;
        const int q = (y >> 1) * 7 + (x >> 1);
        mask_out[(box * BS_N + i) * 196 + t] = keep[box][q] ? 0.0f : 1.0f;
    }
}

// ---------------------------------------------------------------------------
// Launch: fork-join (mask parallel with split+GEMM)
// ---------------------------------------------------------------------------
extern "C" void kernel_launch(void* const* d_in, const int* in_sizes, int n_in,
                              void* d_out, int out_size) {
    const float* attn        = (const float*)d_in[0];   // [8192, 196]
    const int*   pos         = (const int*)d_in[1];     // [8192, 3, 4]
    const float* image_embed = (const float*)d_in[2];   // [16384, 768]
    const float* Wm          = (const float*)d_in[3];   // [400, 768]
    const float* bias        = (const float*)d_in[4];   // [400]

    float* logits = (float*)d_out;                      // [16384, 400]
    float* mask   = (float*)d_out + LOGITS_ELEMS;       // [16384, 196]

    cudaFuncSetAttribute(gemm_hmma_kernel,
                         cudaFuncAttributeMaxDynamicSharedMemorySize,
                         SMEM_GEMM_TOTAL);

    cudaStream_t s2 = nullptr;
    cudaEvent_t  e1 = nullptr, e2 = nullptr;
    bool forked =
        (cudaStreamCreateWithFlags(&s2, cudaStreamNonBlocking) == cudaSuccess) &&
        (cudaEventCreateWithFlags(&e1, cudaEventDisableTiming) == cudaSuccess) &&
        (cudaEventCreateWithFlags(&e2, cudaEventDisableTiming) == cudaSuccess);

    if (forked) {
        forked = (cudaEventRecord(e1, (cudaStream_t)0) == cudaSuccess) &&
                 (cudaStreamWaitEvent(s2, e1, 0) == cudaSuccess);
    }

    if (forked) {
        mask_kernel<<<BS_N, 416, 0, s2>>>(attn, pos, mask);
        cudaEventRecord(e2, s2);
    }

    split_kernel<<<(SPLIT_GROUPS + 255) / 256, 256>>>(image_embed, Wm);

    dim3 ggrid(NUM_CLASSES / BN, M_TOTAL / BM);
    gemm_hmma_kernel<<<ggrid, 256, SMEM_GEMM_TOTAL>>>(bias, logits);

    if (forked) {
        cudaStreamWaitEvent((cudaStream_t)0, e2, 0);
    } else {
        mask_kernel<<<BS_N, 416>>>(attn, pos, mask);
    }
}

// round 9
// speedup vs baseline: 2.7507x; 1.0407x over previous
#include <cuda_runtime.h>
#include <cuda_bf16.h>
#include <cstdint>

// ---------------------------------------------------------------------------
// Problem constants
// ---------------------------------------------------------------------------
#define BS_N        8192
#define NUM_CLASSES 400
#define DIM         768
#define M_TOTAL     (2 * BS_N)          // 16384 rows
#define LOGITS_ELEMS (M_TOTAL * NUM_CLASSES)

// ---------------------------------------------------------------------------
// Scratch: bf16 hi/lo splits of A (image_embed) and W
// ---------------------------------------------------------------------------
__device__ __nv_bfloat16 g_Ahi[(size_t)M_TOTAL * DIM];
__device__ __nv_bfloat16 g_Alo[(size_t)M_TOTAL * DIM];
__device__ __nv_bfloat16 g_Whi[(size_t)NUM_CLASSES * DIM];
__device__ __nv_bfloat16 g_Wlo[(size_t)NUM_CLASSES * DIM];

#define NA_ELEMS (M_TOTAL * DIM)        // 12,582,912
#define NW_ELEMS (NUM_CLASSES * DIM)    // 307,200
#define SPLIT_GROUPS ((NA_ELEMS + NW_ELEMS) / 8)

// ---------------------------------------------------------------------------
// Fused split kernel: A then W regions, fp32 -> (bf16 hi, bf16 lo)
// ---------------------------------------------------------------------------
__global__ void __launch_bounds__(256) split_kernel(const float* __restrict__ inA,
                                                    const float* __restrict__ inW) {
    int g = blockIdx.x * 256 + threadIdx.x;
    if (g >= SPLIT_GROUPS) return;

    const float* in;
    __nv_bfloat16 *hi, *lo;
    int i8;
    if (g < NA_ELEMS / 8) {
        in = inA; hi = g_Ahi; lo = g_Alo; i8 = g * 8;
    } else {
        in = inW; hi = g_Whi; lo = g_Wlo; i8 = (g - NA_ELEMS / 8) * 8;
    }

    float4 v0 = *reinterpret_cast<const float4*>(in + i8);
    float4 v1 = *reinterpret_cast<const float4*>(in + i8 + 4);

    float f[8] = {v0.x, v0.y, v0.z, v0.w, v1.x, v1.y, v1.z, v1.w};
    __nv_bfloat16 h[8], l[8];
    #pragma unroll
    for (int j = 0; j < 8; ++j) {
        h[j] = __float2bfloat16(f[j]);
        l[j] = __float2bfloat16(f[j] - __bfloat162float(h[j]));
    }
    *reinterpret_cast<uint4*>(hi + i8) = *reinterpret_cast<const uint4*>(h);
    *reinterpret_cast<uint4*>(lo + i8) = *reinterpret_cast<const uint4*>(l);
}

// ---------------------------------------------------------------------------
// HMMA GEMM (unchanged from round 8): CTA 128x80x64, 8 warps, SW128 swizzle,
// ldmatrix, double-buffered stages + double-buffered register fragments.
// ---------------------------------------------------------------------------
#define BM 128
#define BN 80
#define BK 64
#define NCHUNKS (DIM / BK)                // 12

#define SA_H 0
#define SA_L (SA_H + BM * 128)            // 16384
#define SB_H (SA_L + BM * 128)            // 32768
#define SB_L (SB_H + BN * 128)            // 43008
#define STAGE_B (SB_L + BN * 128)         // 53248
#define SMEM_GEMM_TOTAL (2 * STAGE_B)     // 106496

__device__ __forceinline__ uint32_t smem_u32(const void* p) {
    uint32_t a;
    asm("{ .reg .u64 t; cvta.to.shared.u64 t, %1; cvt.u32.u64 %0, t; }"
        : "=r"(a) : "l"(p));
    return a;
}

__device__ __forceinline__ void cp_async16(uint32_t s, const void* g) {
    asm volatile("cp.async.cg.shared.global [%0], [%1], 16;" :: "r"(s), "l"(g));
}

__device__ __forceinline__ void cp_commit() {
    asm volatile("cp.async.commit_group;" ::: "memory");
}

template <int N>
__device__ __forceinline__ void cp_wait() {
    asm volatile("cp.async.wait_group %0;" :: "n"(N) : "memory");
}

__device__ __forceinline__ void ldsm_x4(uint32_t& r0, uint32_t& r1,
                                        uint32_t& r2, uint32_t& r3, uint32_t a) {
    asm volatile("ldmatrix.sync.aligned.m8n8.x4.shared.b16 {%0,%1,%2,%3}, [%4];"
                 : "=r"(r0), "=r"(r1), "=r"(r2), "=r"(r3) : "r"(a));
}

__device__ __forceinline__ void ldsm_x2(uint32_t& r0, uint32_t& r1, uint32_t a) {
    asm volatile("ldmatrix.sync.aligned.m8n8.x2.shared.b16 {%0,%1}, [%2];"
                 : "=r"(r0), "=r"(r1) : "r"(a));
}

__device__ __forceinline__ void mma16816(float* c, uint32_t a0, uint32_t a1,
                                         uint32_t a2, uint32_t a3,
                                         uint32_t b0, uint32_t b1) {
    asm volatile(
        "mma.sync.aligned.m16n8k16.row.col.f32.bf16.bf16.f32 "
        "{%0,%1,%2,%3}, {%4,%5,%6,%7}, {%8,%9}, {%0,%1,%2,%3};"
        : "+f"(c[0]), "+f"(c[1]), "+f"(c[2]), "+f"(c[3])
        : "r"(a0), "r"(a1), "r"(a2), "r"(a3), "r"(b0), "r"(b1));
}

struct Frags {
    uint32_t ah[2][4], al[2][4];
    uint32_t bh[5][2], bl[5][2];
};

__device__ __forceinline__ void load_stage(uint32_t sbase,
                                           const __nv_bfloat16* Ah,
                                           const __nv_bfloat16* Al,
                                           const __nv_bfloat16* Bh,
                                           const __nv_bfloat16* Bl,
                                           int k0, int tid) {
    #pragma unroll
    for (int j = 0; j < 4; ++j) {
        int idx = tid + j * 256;
        int row = idx >> 3;
        int seg = idx & 7;
        size_t goff = (size_t)row * DIM + k0 + seg * 8;
        uint32_t sw = (uint32_t)row * 128 + (uint32_t)((seg ^ (row & 7)) << 4);
        cp_async16(sbase + SA_H + sw, Ah + goff);
        cp_async16(sbase + SA_L + sw, Al + goff);
    }
    #pragma unroll
    for (int j = 0; j < 2; ++j) {
        int idx = tid + j * 256;
        int row = idx >> 3;
        int seg = idx & 7;
        size_t goff = (size_t)row * DIM + k0 + seg * 8;
        uint32_t sw = (uint32_t)row * 128 + (uint32_t)((seg ^ (row & 7)) << 4);
        cp_async16(sbase + SB_H + sw, Bh + goff);
        cp_async16(sbase + SB_L + sw, Bl + goff);
    }
    if (tid < 128) {
        int idx = 512 + tid;
        int row = idx >> 3;
        int seg = idx & 7;
        size_t goff = (size_t)row * DIM + k0 + seg * 8;
        uint32_t sw = (uint32_t)row * 128 + (uint32_t)((seg ^ (row & 7)) << 4);
        cp_async16(sbase + SB_H + sw, Bh + goff);
        cp_async16(sbase + SB_L + sw, Bl + goff);
    }
    cp_commit();
}

__global__ void __launch_bounds__(256, 2) gemm_hmma_kernel(const float* __restrict__ bias,
                                                           float* __restrict__ C) {
    extern __shared__ char smem[];
    const int tid    = threadIdx.x;
    const int warp   = tid >> 5;
    const int lane   = tid & 31;
    const int warp_m = warp >> 1;
    const int warp_n = warp & 1;
    const uint32_t sb = smem_u32(smem);

    const int m0 = blockIdx.y * BM;
    const int n0 = blockIdx.x * BN;

    const __nv_bfloat16* Ah = g_Ahi + (size_t)m0 * DIM;
    const __nv_bfloat16* Al = g_Alo + (size_t)m0 * DIM;
    const __nv_bfloat16* Bh = g_Whi + (size_t)n0 * DIM;
    const __nv_bfloat16* Bl = g_Wlo + (size_t)n0 * DIM;

    float acc[2][5][4];
    #pragma unroll
    for (int mt = 0; mt < 2; ++mt)
        #pragma unroll
        for (int nt = 0; nt < 5; ++nt)
            #pragma unroll
            for (int j = 0; j < 4; ++j)
                acc[mt][nt][j] = 0.0f;

    const int lmat = lane >> 3;
    const int li   = lane & 7;
    const int a_rlo   = (lmat & 1) << 3;
    const int a_shalf = lmat >> 1;
    uint32_t a_row[2];
    #pragma unroll
    for (int mt = 0; mt < 2; ++mt)
        a_row[mt] = (uint32_t)(warp_m * 32 + mt * 16 + a_rlo + li) * 128;
    const int b_shalf = lmat & 1;
    uint32_t b_row[2];
    #pragma unroll
    for (int p = 0; p < 2; ++p)
        b_row[p] = (uint32_t)(warp_n * 40 + (p * 2 + (lmat >> 1)) * 8 + li) * 128;
    const int b2_shalf = lmat & 1;
    const uint32_t b2_row = (uint32_t)(warp_n * 40 + 32 + li) * 128;

    auto load_frags = [&](uint32_t cur, int k16, Frags& f) {
        const int s2 = k16 * 2;
        uint32_t axor = (uint32_t)((((s2 + a_shalf) ^ li) & 7) << 4);
        #pragma unroll
        for (int mt = 0; mt < 2; ++mt) {
            ldsm_x4(f.ah[mt][0], f.ah[mt][1], f.ah[mt][2], f.ah[mt][3],
                    cur + SA_H + a_row[mt] + axor);
            ldsm_x4(f.al[mt][0], f.al[mt][1], f.al[mt][2], f.al[mt][3],
                    cur + SA_L + a_row[mt] + axor);
        }
        uint32_t bxor = (uint32_t)((((s2 + b_shalf) ^ li) & 7) << 4);
        #pragma unroll
        for (int p = 0; p < 2; ++p) {
            ldsm_x4(f.bh[p * 2][0], f.bh[p * 2][1], f.bh[p * 2 + 1][0], f.bh[p * 2 + 1][1],
                    cur + SB_H + b_row[p] + bxor);
            ldsm_x4(f.bl[p * 2][0], f.bl[p * 2][1], f.bl[p * 2 + 1][0], f.bl[p * 2 + 1][1],
                    cur + SB_L + b_row[p] + bxor);
        }
        uint32_t b2xor = (uint32_t)((((s2 + b2_shalf) ^ li) & 7) << 4);
        ldsm_x2(f.bh[4][0], f.bh[4][1], cur + SB_H + b2_row + b2xor);
        ldsm_x2(f.bl[4][0], f.bl[4][1], cur + SB_L + b2_row + b2xor);
    };

    auto do_mmas = [&](Frags& f) {
        #pragma unroll
        for (int mt = 0; mt < 2; ++mt)
            #pragma unroll
            for (int nt = 0; nt < 5; ++nt) {
                mma16816(acc[mt][nt], f.ah[mt][0], f.ah[mt][1], f.ah[mt][2], f.ah[mt][3],
                         f.bh[nt][0], f.bh[nt][1]);
                mma16816(acc[mt][nt], f.ah[mt][0], f.ah[mt][1], f.ah[mt][2], f.ah[mt][3],
                         f.bl[nt][0], f.bl[nt][1]);
                mma16816(acc[mt][nt], f.al[mt][0], f.al[mt][1], f.al[mt][2], f.al[mt][3],
                         f.bh[nt][0], f.bh[nt][1]);
            }
    };

    load_stage(sb, Ah, Al, Bh, Bl, 0, tid);

    Frags f0, f1;
    for (int c = 0; c < NCHUNKS; ++c) {
        const uint32_t cur = sb + (uint32_t)(c & 1) * STAGE_B;
        if (c + 1 < NCHUNKS) {
            load_stage(sb + (uint32_t)((c + 1) & 1) * STAGE_B, Ah, Al, Bh, Bl,
                       (c + 1) * BK, tid);
            cp_wait<1>();
        } else {
            cp_wait<0>();
        }
        __syncthreads();

        load_frags(cur, 0, f0);
        load_frags(cur, 1, f1);
        do_mmas(f0);
        load_frags(cur, 2, f0);
        do_mmas(f1);
        load_frags(cur, 3, f1);
        do_mmas(f0);
        do_mmas(f1);

        __syncthreads();
    }

    const int fr = lane >> 2;
    const int fc = (lane & 3) * 2;
    #pragma unroll
    for (int mt = 0; mt < 2; ++mt) {
        int row = m0 + warp_m * 32 + mt * 16 + fr;
        #pragma unroll
        for (int nt = 0; nt < 5; ++nt) {
            int col = n0 + warp_n * 40 + nt * 8 + fc;
            float b0 = __ldg(bias + col);
            float b1 = __ldg(bias + col + 1);
            float2 v0 = make_float2(acc[mt][nt][0] + b0, acc[mt][nt][1] + b1);
            float2 v1 = make_float2(acc[mt][nt][2] + b0, acc[mt][nt][3] + b1);
            *reinterpret_cast<float2*>(&C[(size_t)row * NUM_CLASSES + col]) = v0;
            *reinterpret_cast<float2*>(&C[(size_t)(row + 8) * NUM_CLASSES + col]) = v1;
        }
    }
}

// ---------------------------------------------------------------------------
// Mask kernel — 416 threads; y-axis table entries premultiplied by 14
// (integer-only change; FP expression trees identical -> bit-exact output).
// ---------------------------------------------------------------------------
__device__ __forceinline__ float bilin_combine(const float* __restrict__ m,
                                               int rm0, int rm1, int c0, int c1,
                                               float fy, float fx) {
    float g00 = m[rm0 + c0];
    float g01 = m[rm0 + c1];
    float g10 = m[rm1 + c0];
    float g11 = m[rm1 + c1];
    return g00 * (1.0f - fy) * (1.0f - fx)
         + g01 * (1.0f - fy) * fx
         + g10 * fy * (1.0f - fx)
         + g11 * fy * fx;
}

__global__ void __launch_bounds__(416) mask_kernel(const float* __restrict__ attn,
                                                   const int* __restrict__ pos,
                                                   float* __restrict__ mask_out) {
    const int i   = blockIdx.x;
    const int tid = threadIdx.x;

    __shared__ float m14[196];
    __shared__ float cm[2][196];
    __shared__ unsigned long long key[2][49];
    __shared__ int   keep[2][49];
    __shared__ float t_w[2][2][14];
    __shared__ float t_f0[2][2][14];
    __shared__ float t_f1[2][2][14];
    __shared__ int   t_i00[2][2][14];    // axis 0: r0*14 ; axis 1: c0
    __shared__ int   t_i01[2][2][14];
    __shared__ int   t_i10[2][2][14];
    __shared__ int   t_i11[2][2][14];

    if (tid < 196) m14[tid] = attn[i * 196 + tid];

    if (tid < 56) {
        const int s    = tid;
        const int pbox = s / 28;
        const int rem  = s - pbox * 28;
        const int axis = rem / 14;
        const int idx  = rem - axis * 14;
        const int mul  = axis ? 1 : 14;     // premultiply row indices

        const int* p = pos + i * 12;
        const int oT = p[pbox * 4 + 0];
        const int oL = p[pbox * 4 + 1];
        const int oHi = p[pbox * 4 + 2];
        const int oWi = p[pbox * 4 + 3];
        const int e0 = p[8], e1 = p[9], e2 = p[10], e3 = p[11];

        const float dimO = axis ? (float)oWi : (float)oHi;
        const float off  = axis ? (float)(oL - e1) : (float)(oT - e0);
        const float dimE = axis ? (float)e3 : (float)e2;

        float ty = fmaxf(((float)idx + 0.5f) * dimO / 14.0f - 0.5f, 0.0f);
        float y0 = floorf(ty);
        float y1 = fminf(y0 + 1.0f, dimO - 1.0f);
        t_w[pbox][axis][idx] = ty - y0;
        float Y0 = off + y0;
        float Y1 = off + y1;

        {
            float sy  = fmaxf((Y0 + 0.5f) * 14.0f / dimE - 0.5f, 0.0f);
            float r0f = floorf(sy);
            int r0 = (int)r0f;
            int r1 = min(r0 + 1, 13);
            t_f0[pbox][axis][idx]  = sy - r0f;
            t_i00[pbox][axis][idx] = r0 * mul;
            t_i01[pbox][axis][idx] = r1 * mul;
        }
        {
            float sy  = fmaxf((Y1 + 0.5f) * 14.0f / dimE - 0.5f, 0.0f);
            float r0f = floorf(sy);
            int r0 = (int)r0f;
            int r1 = min(r0 + 1, 13);
            t_f1[pbox][axis][idx]  = sy - r0f;
            t_i10[pbox][axis][idx] = r0 * mul;
            t_i11[pbox][axis][idx] = r1 * mul;
        }
    }
    __syncthreads();

    const int box = tid / 208;
    const int t   = tid - box * 208;

    if (t < 196) {
        const int y = t / 14;
        const int x = t - y * 14;

        float wy  = t_w[box][0][y];
        float wx  = t_w[box][1][x];
        float fyA = t_f0[box][0][y], fyB = t_f1[box][0][y];
        float fxA = t_f0[box][1][x], fxB = t_f1[box][1][x];
        int rA0 = t_i00[box][0][y], rA1 = t_i01[box][0][y];
        int rB0 = t_i10[box][0][y], rB1 = t_i11[box][0][y];
        int cA0 = t_i00[box][1][x], cA1 = t_i01[box][1][x];
        int cB0 = t_i10[box][1][x], cB1 = t_i11[box][1][x];

        float v00 = bilin_combine(m14, rA0, rA1, cA0, cA1, fyA, fxA);
        float v01 = bilin_combine(m14, rA0, rA1, cB0, cB1, fyA, fxB);
        float v10 = bilin_combine(m14, rB0, rB1, cA0, cA1, fyB, fxA);
        float v11 = bilin_combine(m14, rB0, rB1, cB0, cB1, fyB, fxB);

        cm[box][t] = v00 * (1.0f - wy) * (1.0f - wx)
                   + v01 * (1.0f - wy) * wx
                   + v10 * wy * (1.0f - wx)
                   + v11 * wy * wx;
    }
    __syncthreads();

    if (t < 49) {
        const int qy = t / 7;
        const int qx = t - qy * 7;
        const float* c = cm[box];
        float s = (c[(2 * qy) * 14 + 2 * qx] + c[(2 * qy) * 14 + 2 * qx + 1]
                 + c[(2 * qy + 1) * 14 + 2 * qx] + c[(2 * qy + 1) * 14 + 2 * qx + 1]) * 0.25f;
        key[box][t] = ((unsigned long long)__float_as_uint(s) << 6)
                    | (unsigned long long)(48 - t);
    }
    __syncthreads();

    if (t < 49) {
        const unsigned long long kv = key[box][t];
        int rank = 0;
        #pragma unroll
        for (int j = 0; j < 49; ++j)
            rank += (key[box][j] > kv);
        keep[box][t] = (rank < 25);
    }
    __syncthreads();

    if (t < 196) {
        const int y = t / 14;
        const int x = t - y * 14;
        const int q = (y >> 1) * 7 + (x >> 1);
        mask_out[(box * BS_N + i) * 196 + t] = keep[box][q] ? 0.0f : 1.0f;
    }
}

// ---------------------------------------------------------------------------
// Launch: fork-join, but mask enqueued LAST so it backfills the gemm's
// wave tail instead of flooding the SMs first (gemm at 2 CTAs/SM uses the
// whole register file — no co-residency is possible, only tail overlap).
// ---------------------------------------------------------------------------
extern "C" void kernel_launch(void* const* d_in, const int* in_sizes, int n_in,
                              void* d_out, int out_size) {
    const float* attn        = (const float*)d_in[0];   // [8192, 196]
    const int*   pos         = (const int*)d_in[1];     // [8192, 3, 4]
    const float* image_embed = (const float*)d_in[2];   // [16384, 768]
    const float* Wm          = (const float*)d_in[3];   // [400, 768]
    const float* bias        = (const float*)d_in[4];   // [400]

    float* logits = (float*)d_out;                      // [16384, 400]
    float* mask   = (float*)d_out + LOGITS_ELEMS;       // [16384, 196]

    cudaFuncSetAttribute(gemm_hmma_kernel,
                         cudaFuncAttributeMaxDynamicSharedMemorySize,
                         SMEM_GEMM_TOTAL);

    cudaStream_t s2 = nullptr;
    cudaEvent_t  e1 = nullptr, e2 = nullptr;
    bool forked =
        (cudaStreamCreateWithFlags(&s2, cudaStreamNonBlocking) == cudaSuccess) &&
        (cudaEventCreateWithFlags(&e1, cudaEventDisableTiming) == cudaSuccess) &&
        (cudaEventCreateWithFlags(&e2, cudaEventDisableTiming) == cudaSuccess);

    if (forked) {
        forked = (cudaEventRecord(e1, (cudaStream_t)0) == cudaSuccess) &&
                 (cudaStreamWaitEvent(s2, e1, 0) == cudaSuccess);
    }

    // Main branch first: split feeds gemm.
    split_kernel<<<(SPLIT_GROUPS + 255) / 256, 256>>>(image_embed, Wm);
    dim3 ggrid(NUM_CLASSES / BN, M_TOTAL / BM);
    gemm_hmma_kernel<<<ggrid, 256, SMEM_GEMM_TOTAL>>>(bias, logits);

    if (forked) {
        // Mask enqueued last: backfills SMs as gemm waves drain.
        mask_kernel<<<BS_N, 416, 0, s2>>>(attn, pos, mask);
        cudaEventRecord(e2, s2);
        cudaStreamWaitEvent((cudaStream_t)0, e2, 0);
    } else {
        mask_kernel<<<BS_N, 416>>>(attn, pos, mask);
    }
}

// round 10
// speedup vs baseline: 3.0883x; 1.1227x over previous
#include <cuda_runtime.h>
#include <cuda_fp16.h>
#include <cstdint>

// ---------------------------------------------------------------------------
// Problem constants
// ---------------------------------------------------------------------------
#define BS_N        8192
#define NUM_CLASSES 400
#define DIM         768
#define M_TOTAL     (2 * BS_N)          // 16384 rows
#define LOGITS_ELEMS (M_TOTAL * NUM_CLASSES)

// ---------------------------------------------------------------------------
// Scratch: fp16 A (hi only) and fp16 W (hi + lo)
// ---------------------------------------------------------------------------
__device__ __half g_Ah[(size_t)M_TOTAL * DIM];
__device__ __half g_Wh[(size_t)NUM_CLASSES * DIM];
__device__ __half g_Wl[(size_t)NUM_CLASSES * DIM];

#define NA_ELEMS (M_TOTAL * DIM)        // 12,582,912
#define NW_ELEMS (NUM_CLASSES * DIM)    // 307,200
#define SPLIT_GROUPS ((NA_ELEMS + NW_ELEMS) / 8)

// ---------------------------------------------------------------------------
// Split kernel: A -> fp16 (hi only);  W -> fp16 hi + fp16 lo
// ---------------------------------------------------------------------------
__global__ void __launch_bounds__(256) split_kernel(const float* __restrict__ inA,
                                                    const float* __restrict__ inW) {
    int g = blockIdx.x * 256 + threadIdx.x;
    if (g >= SPLIT_GROUPS) return;

    if (g < NA_ELEMS / 8) {
        int i8 = g * 8;
        float4 v0 = *reinterpret_cast<const float4*>(inA + i8);
        float4 v1 = *reinterpret_cast<const float4*>(inA + i8 + 4);
        float f[8] = {v0.x, v0.y, v0.z, v0.w, v1.x, v1.y, v1.z, v1.w};
        __half h[8];
        #pragma unroll
        for (int j = 0; j < 8; ++j) h[j] = __float2half_rn(f[j]);
        *reinterpret_cast<uint4*>(g_Ah + i8) = *reinterpret_cast<const uint4*>(h);
    } else {
        int i8 = (g - NA_ELEMS / 8) * 8;
        float4 v0 = *reinterpret_cast<const float4*>(inW + i8);
        float4 v1 = *reinterpret_cast<const float4*>(inW + i8 + 4);
        float f[8] = {v0.x, v0.y, v0.z, v0.w, v1.x, v1.y, v1.z, v1.w};
        __half h[8], l[8];
        #pragma unroll
        for (int j = 0; j < 8; ++j) {
            h[j] = __float2half_rn(f[j]);
            l[j] = __float2half_rn(f[j] - __half2float(h[j]));
        }
        *reinterpret_cast<uint4*>(g_Wh + i8) = *reinterpret_cast<const uint4*>(h);
        *reinterpret_cast<uint4*>(g_Wl + i8) = *reinterpret_cast<const uint4*>(l);
    }
}

// ---------------------------------------------------------------------------
// HMMA GEMM: C = A @ W^T + b, fp16 2-term (ah*bh + ah*bl), fp32 accum.
// CTA 128x80x64, 8 warps. SW128 swizzle, ldmatrix, double-buffered stages +
// double-buffered register fragments.
// ---------------------------------------------------------------------------
#define BM 128
#define BN 80
#define BK 64
#define NCHUNKS (DIM / BK)                // 12

#define SA_H 0
#define SB_H (SA_H + BM * 128)            // 16384
#define SB_L (SB_H + BN * 128)            // 26624
#define STAGE_B (SB_L + BN * 128)         // 36864
#define SMEM_GEMM_TOTAL (2 * STAGE_B)     // 73728

__device__ __forceinline__ uint32_t smem_u32(const void* p) {
    uint32_t a;
    asm("{ .reg .u64 t; cvta.to.shared.u64 t, %1; cvt.u32.u64 %0, t; }"
        : "=r"(a) : "l"(p));
    return a;
}

__device__ __forceinline__ void cp_async16(uint32_t s, const void* g) {
    asm volatile("cp.async.cg.shared.global [%0], [%1], 16;" :: "r"(s), "l"(g));
}

__device__ __forceinline__ void cp_commit() {
    asm volatile("cp.async.commit_group;" ::: "memory");
}

template <int N>
__device__ __forceinline__ void cp_wait() {
    asm volatile("cp.async.wait_group %0;" :: "n"(N) : "memory");
}

__device__ __forceinline__ void ldsm_x4(uint32_t& r0, uint32_t& r1,
                                        uint32_t& r2, uint32_t& r3, uint32_t a) {
    asm volatile("ldmatrix.sync.aligned.m8n8.x4.shared.b16 {%0,%1,%2,%3}, [%4];"
                 : "=r"(r0), "=r"(r1), "=r"(r2), "=r"(r3) : "r"(a));
}

__device__ __forceinline__ void ldsm_x2(uint32_t& r0, uint32_t& r1, uint32_t a) {
    asm volatile("ldmatrix.sync.aligned.m8n8.x2.shared.b16 {%0,%1}, [%2];"
                 : "=r"(r0), "=r"(r1) : "r"(a));
}

__device__ __forceinline__ void mma16816(float* c, uint32_t a0, uint32_t a1,
                                         uint32_t a2, uint32_t a3,
                                         uint32_t b0, uint32_t b1) {
    asm volatile(
        "mma.sync.aligned.m16n8k16.row.col.f32.f16.f16.f32 "
        "{%0,%1,%2,%3}, {%4,%5,%6,%7}, {%8,%9}, {%0,%1,%2,%3};"
        : "+f"(c[0]), "+f"(c[1]), "+f"(c[2]), "+f"(c[3])
        : "r"(a0), "r"(a1), "r"(a2), "r"(a3), "r"(b0), "r"(b1));
}

struct Frags {
    uint32_t ah[2][4];
    uint32_t bh[5][2], bl[5][2];
};

__device__ __forceinline__ void load_stage(uint32_t sbase,
                                           const __half* Ah,
                                           const __half* Bh,
                                           const __half* Bl,
                                           int k0, int tid) {
    // A: 128 rows x 8 segs of 16B -> 1024 chunks, 4 per thread
    #pragma unroll
    for (int j = 0; j < 4; ++j) {
        int idx = tid + j * 256;
        int row = idx >> 3;
        int seg = idx & 7;
        size_t goff = (size_t)row * DIM + k0 + seg * 8;
        uint32_t sw = (uint32_t)row * 128 + (uint32_t)((seg ^ (row & 7)) << 4);
        cp_async16(sbase + SA_H + sw, Ah + goff);
    }
    // B: 80 rows x 8 segs -> 640 chunks per array
    #pragma unroll
    for (int j = 0; j < 2; ++j) {
        int idx = tid + j * 256;
        int row = idx >> 3;
        int seg = idx & 7;
        size_t goff = (size_t)row * DIM + k0 + seg * 8;
        uint32_t sw = (uint32_t)row * 128 + (uint32_t)((seg ^ (row & 7)) << 4);
        cp_async16(sbase + SB_H + sw, Bh + goff);
        cp_async16(sbase + SB_L + sw, Bl + goff);
    }
    if (tid < 128) {
        int idx = 512 + tid;
        int row = idx >> 3;
        int seg = idx & 7;
        size_t goff = (size_t)row * DIM + k0 + seg * 8;
        uint32_t sw = (uint32_t)row * 128 + (uint32_t)((seg ^ (row & 7)) << 4);
        cp_async16(sbase + SB_H + sw, Bh + goff);
        cp_async16(sbase + SB_L + sw, Bl + goff);
    }
    cp_commit();
}

__global__ void __launch_bounds__(256, 2) gemm_hmma_kernel(const float* __restrict__ bias,
                                                           float* __restrict__ C) {
    extern __shared__ char smem[];
    const int tid    = threadIdx.x;
    const int warp   = tid >> 5;
    const int lane   = tid & 31;
    const int warp_m = warp >> 1;
    const int warp_n = warp & 1;
    const uint32_t sb = smem_u32(smem);

    const int m0 = blockIdx.y * BM;
    const int n0 = blockIdx.x * BN;

    const __half* Ah = g_Ah + (size_t)m0 * DIM;
    const __half* Bh = g_Wh + (size_t)n0 * DIM;
    const __half* Bl = g_Wl + (size_t)n0 * DIM;

    float acc[2][5][4];
    #pragma unroll
    for (int mt = 0; mt < 2; ++mt)
        #pragma unroll
        for (int nt = 0; nt < 5; ++nt)
            #pragma unroll
            for (int j = 0; j < 4; ++j)
                acc[mt][nt][j] = 0.0f;

    const int lmat = lane >> 3;
    const int li   = lane & 7;
    const int a_rlo   = (lmat & 1) << 3;
    const int a_shalf = lmat >> 1;
    uint32_t a_row[2];
    #pragma unroll
    for (int mt = 0; mt < 2; ++mt)
        a_row[mt] = (uint32_t)(warp_m * 32 + mt * 16 + a_rlo + li) * 128;
    const int b_shalf = lmat & 1;
    uint32_t b_row[2];
    #pragma unroll
    for (int p = 0; p < 2; ++p)
        b_row[p] = (uint32_t)(warp_n * 40 + (p * 2 + (lmat >> 1)) * 8 + li) * 128;
    const int b2_shalf = lmat & 1;
    const uint32_t b2_row = (uint32_t)(warp_n * 40 + 32 + li) * 128;

    auto load_frags = [&](uint32_t cur, int k16, Frags& f) {
        const int s2 = k16 * 2;
        uint32_t axor = (uint32_t)((((s2 + a_shalf) ^ li) & 7) << 4);
        #pragma unroll
        for (int mt = 0; mt < 2; ++mt)
            ldsm_x4(f.ah[mt][0], f.ah[mt][1], f.ah[mt][2], f.ah[mt][3],
                    cur + SA_H + a_row[mt] + axor);
        uint32_t bxor = (uint32_t)((((s2 + b_shalf) ^ li) & 7) << 4);
        #pragma unroll
        for (int p = 0; p < 2; ++p) {
            ldsm_x4(f.bh[p * 2][0], f.bh[p * 2][1], f.bh[p * 2 + 1][0], f.bh[p * 2 + 1][1],
                    cur + SB_H + b_row[p] + bxor);
            ldsm_x4(f.bl[p * 2][0], f.bl[p * 2][1], f.bl[p * 2 + 1][0], f.bl[p * 2 + 1][1],
                    cur + SB_L + b_row[p] + bxor);
        }
        uint32_t b2xor = (uint32_t)((((s2 + b2_shalf) ^ li) & 7) << 4);
        ldsm_x2(f.bh[4][0], f.bh[4][1], cur + SB_H + b2_row + b2xor);
        ldsm_x2(f.bl[4][0], f.bl[4][1], cur + SB_L + b2_row + b2xor);
    };

    auto do_mmas = [&](Frags& f) {
        #pragma unroll
        for (int mt = 0; mt < 2; ++mt)
            #pragma unroll
            for (int nt = 0; nt < 5; ++nt) {
                mma16816(acc[mt][nt], f.ah[mt][0], f.ah[mt][1], f.ah[mt][2], f.ah[mt][3],
                         f.bh[nt][0], f.bh[nt][1]);
                mma16816(acc[mt][nt], f.ah[mt][0], f.ah[mt][1], f.ah[mt][2], f.ah[mt][3],
                         f.bl[nt][0], f.bl[nt][1]);
            }
    };

    load_stage(sb, Ah, Bh, Bl, 0, tid);

    Frags f0, f1;
    for (int c = 0; c < NCHUNKS; ++c) {
        const uint32_t cur = sb + (uint32_t)(c & 1) * STAGE_B;
        if (c + 1 < NCHUNKS) {
            load_stage(sb + (uint32_t)((c + 1) & 1) * STAGE_B, Ah, Bh, Bl,
                       (c + 1) * BK, tid);
            cp_wait<1>();
        } else {
            cp_wait<0>();
        }
        __syncthreads();

        load_frags(cur, 0, f0);
        load_frags(cur, 1, f1);
        do_mmas(f0);
        load_frags(cur, 2, f0);
        do_mmas(f1);
        load_frags(cur, 3, f1);
        do_mmas(f0);
        do_mmas(f1);

        __syncthreads();
    }

    const int fr = lane >> 2;
    const int fc = (lane & 3) * 2;
    #pragma unroll
    for (int mt = 0; mt < 2; ++mt) {
        int row = m0 + warp_m * 32 + mt * 16 + fr;
        #pragma unroll
        for (int nt = 0; nt < 5; ++nt) {
            int col = n0 + warp_n * 40 + nt * 8 + fc;
            float b0 = __ldg(bias + col);
            float b1 = __ldg(bias + col + 1);
            float2 v0 = make_float2(acc[mt][nt][0] + b0, acc[mt][nt][1] + b1);
            float2 v1 = make_float2(acc[mt][nt][2] + b0, acc[mt][nt][3] + b1);
            *reinterpret_cast<float2*>(&C[(size_t)row * NUM_CLASSES + col]) = v0;
            *reinterpret_cast<float2*>(&C[(size_t)(row + 8) * NUM_CLASSES + col]) = v1;
        }
    }
}

// ---------------------------------------------------------------------------
// Mask kernel — warp-autonomous: one warp per (image, box), __syncwarp only.
// Every FP expression is verbatim from the verified bit-exact version; only
// the thread->work mapping changed.
// ---------------------------------------------------------------------------
#define MW_WARPS 8

__device__ __forceinline__ float bilin_combine(const float* __restrict__ m,
                                               int rm0, int rm1, int c0, int c1,
                                               float fy, float fx) {
    float g00 = m[rm0 + c0];
    float g01 = m[rm0 + c1];
    float g10 = m[rm1 + c0];
    float g11 = m[rm1 + c1];
    return g00 * (1.0f - fy) * (1.0f - fx)
         + g01 * (1.0f - fy) * fx
         + g10 * fy * (1.0f - fx)
         + g11 * fy * fx;
}

__global__ void __launch_bounds__(256) mask_kernel(const float* __restrict__ attn,
                                                   const int* __restrict__ pos,
                                                   float* __restrict__ mask_out) {
    const int w    = threadIdx.x >> 5;
    const int lane = threadIdx.x & 31;
    const int pid  = blockIdx.x * MW_WARPS + w;   // 0..16383
    const int i    = pid >> 1;
    const int box  = pid & 1;

    __shared__ float m14[MW_WARPS][196];
    __shared__ float cm[MW_WARPS][196];
    __shared__ unsigned long long key[MW_WARPS][49];
    __shared__ int   keep[MW_WARPS][49];
    __shared__ float t_w[MW_WARPS][2][14];
    __shared__ float t_f0[MW_WARPS][2][14];
    __shared__ float t_f1[MW_WARPS][2][14];
    __shared__ int   t_i00[MW_WARPS][2][14];   // axis 0: r*14 ; axis 1: c
    __shared__ int   t_i01[MW_WARPS][2][14];
    __shared__ int   t_i10[MW_WARPS][2][14];
    __shared__ int   t_i11[MW_WARPS][2][14];

    // Phase 1: attention row into this warp's m14
    for (int t = lane; t < 196; t += 32)
        m14[w][t] = attn[i * 196 + t];

    // Phase 2: weight/index tables (28 entries; lanes 0..27)
    if (lane < 28) {
        const int axis = lane / 14;
        const int idx  = lane - axis * 14;
        const int mul  = axis ? 1 : 14;

        const int* p = pos + i * 12;
        const int oT = p[box * 4 + 0];
        const int oL = p[box * 4 + 1];
        const int oHi = p[box * 4 + 2];
        const int oWi = p[box * 4 + 3];
        const int e0 = p[8], e1 = p[9], e2 = p[10], e3 = p[11];

        const float dimO = axis ? (float)oWi : (float)oHi;
        const float off  = axis ? (float)(oL - e1) : (float)(oT - e0);
        const float dimE = axis ? (float)e3 : (float)e2;

        float ty = fmaxf(((float)idx + 0.5f) * dimO / 14.0f - 0.5f, 0.0f);
        float y0 = floorf(ty);
        float y1 = fminf(y0 + 1.0f, dimO - 1.0f);
        t_w[w][axis][idx] = ty - y0;
        float Y0 = off + y0;
        float Y1 = off + y1;

        {
            float sy  = fmaxf((Y0 + 0.5f) * 14.0f / dimE - 0.5f, 0.0f);
            float r0f = floorf(sy);
            int r0 = (int)r0f;
            int r1 = min(r0 + 1, 13);
            t_f0[w][axis][idx]  = sy - r0f;
            t_i00[w][axis][idx] = r0 * mul;
            t_i01[w][axis][idx] = r1 * mul;
        }
        {
            float sy  = fmaxf((Y1 + 0.5f) * 14.0f / dimE - 0.5f, 0.0f);
            float r0f = floorf(sy);
            int r0 = (int)r0f;
            int r1 = min(r0 + 1, 13);
            t_f1[w][axis][idx]  = sy - r0f;
            t_i10[w][axis][idx] = r0 * mul;
            t_i11[w][axis][idx] = r1 * mul;
        }
    }
    __syncwarp();

    // Phase 3: double-bilinear resample (196 elems)
    for (int t = lane; t < 196; t += 32) {
        const int y = t / 14;
        const int x = t - y * 14;

        float wy  = t_w[w][0][y];
        float wx  = t_w[w][1][x];
        float fyA = t_f0[w][0][y], fyB = t_f1[w][0][y];
        float fxA = t_f0[w][1][x], fxB = t_f1[w][1][x];
        int rA0 = t_i00[w][0][y], rA1 = t_i01[w][0][y];
        int rB0 = t_i10[w][0][y], rB1 = t_i11[w][0][y];
        int cA0 = t_i00[w][1][x], cA1 = t_i01[w][1][x];
        int cB0 = t_i10[w][1][x], cB1 = t_i11[w][1][x];

        float v00 = bilin_combine(m14[w], rA0, rA1, cA0, cA1, fyA, fxA);
        float v01 = bilin_combine(m14[w], rA0, rA1, cB0, cB1, fyA, fxB);
        float v10 = bilin_combine(m14[w], rB0, rB1, cA0, cA1, fyB, fxA);
        float v11 = bilin_combine(m14[w], rB0, rB1, cB0, cB1, fyB, fxB);

        cm[w][t] = v00 * (1.0f - wy) * (1.0f - wx)
                 + v01 * (1.0f - wy) * wx
                 + v10 * wy * (1.0f - wx)
                 + v11 * wy * wx;
    }
    __syncwarp();

    // Phase 4: 2x2 avg-pool + sort keys (49 elems)
    for (int t = lane; t < 49; t += 32) {
        const int qy = t / 7;
        const int qx = t - qy * 7;
        const float* c = cm[w];
        float s = (c[(2 * qy) * 14 + 2 * qx] + c[(2 * qy) * 14 + 2 * qx + 1]
                 + c[(2 * qy + 1) * 14 + 2 * qx] + c[(2 * qy + 1) * 14 + 2 * qx + 1]) * 0.25f;
        key[w][t] = ((unsigned long long)__float_as_uint(s) << 6)
                  | (unsigned long long)(48 - t);
    }
    __syncwarp();

    // Phase 5: exact rank-based top-25 keep
    for (int t = lane; t < 49; t += 32) {
        const unsigned long long kv = key[w][t];
        int rank = 0;
        #pragma unroll
        for (int j = 0; j < 49; ++j)
            rank += (key[w][j] > kv);
        keep[w][t] = (rank < 25);
    }
    __syncwarp();

    // Phase 6: 2x upsample + write
    for (int t = lane; t < 196; t += 32) {
        const int y = t / 14;
        const int x = t - y * 14;
        const int q = (y >> 1) * 7 + (x >> 1);
        mask_out[(box * BS_N + i) * 196 + t] = keep[w][q] ? 0.0f : 1.0f;
    }
}

// ---------------------------------------------------------------------------
// Launch: split -> gemm on main branch; mask forked, enqueued last so it
// backfills the gemm's wave tail.
// ---------------------------------------------------------------------------
extern "C" void kernel_launch(void* const* d_in, const int* in_sizes, int n_in,
                              void* d_out, int out_size) {
    const float* attn        = (const float*)d_in[0];   // [8192, 196]
    const int*   pos         = (const int*)d_in[1];     // [8192, 3, 4]
    const float* image_embed = (const float*)d_in[2];   // [16384, 768]
    const float* Wm          = (const float*)d_in[3];   // [400, 768]
    const float* bias        = (const float*)d_in[4];   // [400]

    float* logits = (float*)d_out;                      // [16384, 400]
    float* mask   = (float*)d_out + LOGITS_ELEMS;       // [16384, 196]

    cudaFuncSetAttribute(gemm_hmma_kernel,
                         cudaFuncAttributeMaxDynamicSharedMemorySize,
                         SMEM_GEMM_TOTAL);

    cudaStream_t s2 = nullptr;
    cudaEvent_t  e1 = nullptr, e2 = nullptr;
    bool forked =
        (cudaStreamCreateWithFlags(&s2, cudaStreamNonBlocking) == cudaSuccess) &&
        (cudaEventCreateWithFlags(&e1, cudaEventDisableTiming) == cudaSuccess) &&
        (cudaEventCreateWithFlags(&e2, cudaEventDisableTiming) == cudaSuccess);

    if (forked) {
        forked = (cudaEventRecord(e1, (cudaStream_t)0) == cudaSuccess) &&
                 (cudaStreamWaitEvent(s2, e1, 0) == cudaSuccess);
    }

    split_kernel<<<(SPLIT_GROUPS + 255) / 256, 256>>>(image_embed, Wm);
    dim3 ggrid(NUM_CLASSES / BN, M_TOTAL / BM);
    gemm_hmma_kernel<<<ggrid, 256, SMEM_GEMM_TOTAL>>>(bias, logits);

    if (forked) {
        mask_kernel<<<(2 * BS_N) / MW_WARPS, 256, 0, s2>>>(attn, pos, mask);
        cudaEventRecord(e2, s2);
        cudaStreamWaitEvent((cudaStream_t)0, e2, 0);
    } else {
        mask_kernel<<<(2 * BS_N) / MW_WARPS, 256>>>(attn, pos, mask);
    }
}

// round 11
// speedup vs baseline: 3.5886x; 1.1620x over previous
#include <cuda_runtime.h>
#include <cuda_fp16.h>
#include <cstdint>

// ---------------------------------------------------------------------------
// Problem constants
// ---------------------------------------------------------------------------
#define BS_N        8192
#define NUM_CLASSES 400
#define DIM         768
#define M_TOTAL     (2 * BS_N)          // 16384 rows
#define LOGITS_ELEMS (M_TOTAL * NUM_CLASSES)

// ---------------------------------------------------------------------------
// Scratch: fp16 A and fp16 W (single term each; calibrated err ~2.9e-4 << 1e-3)
// ---------------------------------------------------------------------------
__device__ __half g_Ah[(size_t)M_TOTAL * DIM];
__device__ __half g_Wh[(size_t)NUM_CLASSES * DIM];

#define NA_ELEMS (M_TOTAL * DIM)        // 12,582,912
#define NW_ELEMS (NUM_CLASSES * DIM)    // 307,200
#define SPLIT_GROUPS ((NA_ELEMS + NW_ELEMS) / 8)

// ---------------------------------------------------------------------------
// Split kernel: fp32 -> fp16 (A and W)
// ---------------------------------------------------------------------------
__global__ void __launch_bounds__(256) split_kernel(const float* __restrict__ inA,
                                                    const float* __restrict__ inW) {
    int g = blockIdx.x * 256 + threadIdx.x;
    if (g >= SPLIT_GROUPS) return;

    const float* in;
    __half* out;
    int i8;
    if (g < NA_ELEMS / 8) {
        in = inA; out = g_Ah; i8 = g * 8;
    } else {
        in = inW; out = g_Wh; i8 = (g - NA_ELEMS / 8) * 8;
    }

    float4 v0 = *reinterpret_cast<const float4*>(in + i8);
    float4 v1 = *reinterpret_cast<const float4*>(in + i8 + 4);
    float f[8] = {v0.x, v0.y, v0.z, v0.w, v1.x, v1.y, v1.z, v1.w};
    __half h[8];
    #pragma unroll
    for (int j = 0; j < 8; ++j) h[j] = __float2half_rn(f[j]);
    *reinterpret_cast<uint4*>(out + i8) = *reinterpret_cast<const uint4*>(h);
}

// ---------------------------------------------------------------------------
// HMMA GEMM: C = A @ W^T + b, pure fp16 inputs, fp32 accum.
// CTA 128x80x64, 8 warps. SW128 swizzle, ldmatrix, double-buffered stages +
// double-buffered register fragments.
// ---------------------------------------------------------------------------
#define BM 128
#define BN 80
#define BK 64
#define NCHUNKS (DIM / BK)                // 12

#define SA_H 0
#define SB_H (SA_H + BM * 128)            // 16384
#define STAGE_B (SB_H + BN * 128)         // 26624
#define SMEM_GEMM_TOTAL (2 * STAGE_B)     // 53248

__device__ __forceinline__ uint32_t smem_u32(const void* p) {
    uint32_t a;
    asm("{ .reg .u64 t; cvta.to.shared.u64 t, %1; cvt.u32.u64 %0, t; }"
        : "=r"(a) : "l"(p));
    return a;
}

__device__ __forceinline__ void cp_async16(uint32_t s, const void* g) {
    asm volatile("cp.async.cg.shared.global [%0], [%1], 16;" :: "r"(s), "l"(g));
}

__device__ __forceinline__ void cp_commit() {
    asm volatile("cp.async.commit_group;" ::: "memory");
}

template <int N>
__device__ __forceinline__ void cp_wait() {
    asm volatile("cp.async.wait_group %0;" :: "n"(N) : "memory");
}

__device__ __forceinline__ void ldsm_x4(uint32_t& r0, uint32_t& r1,
                                        uint32_t& r2, uint32_t& r3, uint32_t a) {
    asm volatile("ldmatrix.sync.aligned.m8n8.x4.shared.b16 {%0,%1,%2,%3}, [%4];"
                 : "=r"(r0), "=r"(r1), "=r"(r2), "=r"(r3) : "r"(a));
}

__device__ __forceinline__ void ldsm_x2(uint32_t& r0, uint32_t& r1, uint32_t a) {
    asm volatile("ldmatrix.sync.aligned.m8n8.x2.shared.b16 {%0,%1}, [%2];"
                 : "=r"(r0), "=r"(r1) : "r"(a));
}

__device__ __forceinline__ void mma16816(float* c, uint32_t a0, uint32_t a1,
                                         uint32_t a2, uint32_t a3,
                                         uint32_t b0, uint32_t b1) {
    asm volatile(
        "mma.sync.aligned.m16n8k16.row.col.f32.f16.f16.f32 "
        "{%0,%1,%2,%3}, {%4,%5,%6,%7}, {%8,%9}, {%0,%1,%2,%3};"
        : "+f"(c[0]), "+f"(c[1]), "+f"(c[2]), "+f"(c[3])
        : "r"(a0), "r"(a1), "r"(a2), "r"(a3), "r"(b0), "r"(b1));
}

struct Frags {
    uint32_t ah[2][4];
    uint32_t bh[5][2];
};

__device__ __forceinline__ void load_stage(uint32_t sbase,
                                           const __half* Ah,
                                           const __half* Bh,
                                           int k0, int tid) {
    // A: 128 rows x 8 segs of 16B -> 1024 chunks, 4 per thread
    #pragma unroll
    for (int j = 0; j < 4; ++j) {
        int idx = tid + j * 256;
        int row = idx >> 3;
        int seg = idx & 7;
        size_t goff = (size_t)row * DIM + k0 + seg * 8;
        uint32_t sw = (uint32_t)row * 128 + (uint32_t)((seg ^ (row & 7)) << 4);
        cp_async16(sbase + SA_H + sw, Ah + goff);
    }
    // B: 80 rows x 8 segs -> 640 chunks
    #pragma unroll
    for (int j = 0; j < 2; ++j) {
        int idx = tid + j * 256;
        int row = idx >> 3;
        int seg = idx & 7;
        size_t goff = (size_t)row * DIM + k0 + seg * 8;
        uint32_t sw = (uint32_t)row * 128 + (uint32_t)((seg ^ (row & 7)) << 4);
        cp_async16(sbase + SB_H + sw, Bh + goff);
    }
    if (tid < 128) {
        int idx = 512 + tid;
        int row = idx >> 3;
        int seg = idx & 7;
        size_t goff = (size_t)row * DIM + k0 + seg * 8;
        uint32_t sw = (uint32_t)row * 128 + (uint32_t)((seg ^ (row & 7)) << 4);
        cp_async16(sbase + SB_H + sw, Bh + goff);
    }
    cp_commit();
}

__global__ void __launch_bounds__(256, 2) gemm_hmma_kernel(const float* __restrict__ bias,
                                                           float* __restrict__ C) {
    extern __shared__ char smem[];
    const int tid    = threadIdx.x;
    const int warp   = tid >> 5;
    const int lane   = tid & 31;
    const int warp_m = warp >> 1;
    const int warp_n = warp & 1;
    const uint32_t sb = smem_u32(smem);

    const int m0 = blockIdx.y * BM;
    const int n0 = blockIdx.x * BN;

    const __half* Ah = g_Ah + (size_t)m0 * DIM;
    const __half* Bh = g_Wh + (size_t)n0 * DIM;

    float acc[2][5][4];
    #pragma unroll
    for (int mt = 0; mt < 2; ++mt)
        #pragma unroll
        for (int nt = 0; nt < 5; ++nt)
            #pragma unroll
            for (int j = 0; j < 4; ++j)
                acc[mt][nt][j] = 0.0f;

    const int lmat = lane >> 3;
    const int li   = lane & 7;
    const int a_rlo   = (lmat & 1) << 3;
    const int a_shalf = lmat >> 1;
    uint32_t a_row[2];
    #pragma unroll
    for (int mt = 0; mt < 2; ++mt)
        a_row[mt] = (uint32_t)(warp_m * 32 + mt * 16 + a_rlo + li) * 128;
    const int b_shalf = lmat & 1;
    uint32_t b_row[2];
    #pragma unroll
    for (int p = 0; p < 2; ++p)
        b_row[p] = (uint32_t)(warp_n * 40 + (p * 2 + (lmat >> 1)) * 8 + li) * 128;
    const int b2_shalf = lmat & 1;
    const uint32_t b2_row = (uint32_t)(warp_n * 40 + 32 + li) * 128;

    auto load_frags = [&](uint32_t cur, int k16, Frags& f) {
        const int s2 = k16 * 2;
        uint32_t axor = (uint32_t)((((s2 + a_shalf) ^ li) & 7) << 4);
        #pragma unroll
        for (int mt = 0; mt < 2; ++mt)
            ldsm_x4(f.ah[mt][0], f.ah[mt][1], f.ah[mt][2], f.ah[mt][3],
                    cur + SA_H + a_row[mt] + axor);
        uint32_t bxor = (uint32_t)((((s2 + b_shalf) ^ li) & 7) << 4);
        #pragma unroll
        for (int p = 0; p < 2; ++p)
            ldsm_x4(f.bh[p * 2][0], f.bh[p * 2][1], f.bh[p * 2 + 1][0], f.bh[p * 2 + 1][1],
                    cur + SB_H + b_row[p] + bxor);
        uint32_t b2xor = (uint32_t)((((s2 + b2_shalf) ^ li) & 7) << 4);
        ldsm_x2(f.bh[4][0], f.bh[4][1], cur + SB_H + b2_row + b2xor);
    };

    auto do_mmas = [&](Frags& f) {
        #pragma unroll
        for (int mt = 0; mt < 2; ++mt)
            #pragma unroll
            for (int nt = 0; nt < 5; ++nt)
                mma16816(acc[mt][nt], f.ah[mt][0], f.ah[mt][1], f.ah[mt][2], f.ah[mt][3],
                         f.bh[nt][0], f.bh[nt][1]);
    };

    load_stage(sb, Ah, Bh, 0, tid);

    Frags f0, f1;
    for (int c = 0; c < NCHUNKS; ++c) {
        const uint32_t cur = sb + (uint32_t)(c & 1) * STAGE_B;
        if (c + 1 < NCHUNKS) {
            load_stage(sb + (uint32_t)((c + 1) & 1) * STAGE_B, Ah, Bh,
                       (c + 1) * BK, tid);
            cp_wait<1>();
        } else {
            cp_wait<0>();
        }
        __syncthreads();

        load_frags(cur, 0, f0);
        load_frags(cur, 1, f1);
        do_mmas(f0);
        load_frags(cur, 2, f0);
        do_mmas(f1);
        load_frags(cur, 3, f1);
        do_mmas(f0);
        do_mmas(f1);

        __syncthreads();
    }

    const int fr = lane >> 2;
    const int fc = (lane & 3) * 2;
    #pragma unroll
    for (int mt = 0; mt < 2; ++mt) {
        int row = m0 + warp_m * 32 + mt * 16 + fr;
        #pragma unroll
        for (int nt = 0; nt < 5; ++nt) {
            int col = n0 + warp_n * 40 + nt * 8 + fc;
            float b0 = __ldg(bias + col);
            float b1 = __ldg(bias + col + 1);
            float2 v0 = make_float2(acc[mt][nt][0] + b0, acc[mt][nt][1] + b1);
            float2 v1 = make_float2(acc[mt][nt][2] + b0, acc[mt][nt][3] + b1);
            *reinterpret_cast<float2*>(&C[(size_t)row * NUM_CLASSES + col]) = v0;
            *reinterpret_cast<float2*>(&C[(size_t)(row + 8) * NUM_CLASSES + col]) = v1;
        }
    }
}

// ---------------------------------------------------------------------------
// Mask kernel — warp-autonomous (UNCHANGED; FP expressions bit-exact verified)
// ---------------------------------------------------------------------------
#define MW_WARPS 8

__device__ __forceinline__ float bilin_combine(const float* __restrict__ m,
                                               int rm0, int rm1, int c0, int c1,
                                               float fy, float fx) {
    float g00 = m[rm0 + c0];
    float g01 = m[rm0 + c1];
    float g10 = m[rm1 + c0];
    float g11 = m[rm1 + c1];
    return g00 * (1.0f - fy) * (1.0f - fx)
         + g01 * (1.0f - fy) * fx
         + g10 * fy * (1.0f - fx)
         + g11 * fy * fx;
}

__global__ void __launch_bounds__(256) mask_kernel(const float* __restrict__ attn,
                                                   const int* __restrict__ pos,
                                                   float* __restrict__ mask_out) {
    const int w    = threadIdx.x >> 5;
    const int lane = threadIdx.x & 31;
    const int pid  = blockIdx.x * MW_WARPS + w;   // 0..16383
    const int i    = pid >> 1;
    const int box  = pid & 1;

    __shared__ float m14[MW_WARPS][196];
    __shared__ float cm[MW_WARPS][196];
    __shared__ unsigned long long key[MW_WARPS][49];
    __shared__ int   keep[MW_WARPS][49];
    __shared__ float t_w[MW_WARPS][2][14];
    __shared__ float t_f0[MW_WARPS][2][14];
    __shared__ float t_f1[MW_WARPS][2][14];
    __shared__ int   t_i00[MW_WARPS][2][14];
    __shared__ int   t_i01[MW_WARPS][2][14];
    __shared__ int   t_i10[MW_WARPS][2][14];
    __shared__ int   t_i11[MW_WARPS][2][14];

    for (int t = lane; t < 196; t += 32)
        m14[w][t] = attn[i * 196 + t];

    if (lane < 28) {
        const int axis = lane / 14;
        const int idx  = lane - axis * 14;
        const int mul  = axis ? 1 : 14;

        const int* p = pos + i * 12;
        const int oT = p[box * 4 + 0];
        const int oL = p[box * 4 + 1];
        const int oHi = p[box * 4 + 2];
        const int oWi = p[box * 4 + 3];
        const int e0 = p[8], e1 = p[9], e2 = p[10], e3 = p[11];

        const float dimO = axis ? (float)oWi : (float)oHi;
        const float off  = axis ? (float)(oL - e1) : (float)(oT - e0);
        const float dimE = axis ? (float)e3 : (float)e2;

        float ty = fmaxf(((float)idx + 0.5f) * dimO / 14.0f - 0.5f, 0.0f);
        float y0 = floorf(ty);
        float y1 = fminf(y0 + 1.0f, dimO - 1.0f);
        t_w[w][axis][idx] = ty - y0;
        float Y0 = off + y0;
        float Y1 = off + y1;

        {
            float sy  = fmaxf((Y0 + 0.5f) * 14.0f / dimE - 0.5f, 0.0f);
            float r0f = floorf(sy);
            int r0 = (int)r0f;
            int r1 = min(r0 + 1, 13);
            t_f0[w][axis][idx]  = sy - r0f;
            t_i00[w][axis][idx] = r0 * mul;
            t_i01[w][axis][idx] = r1 * mul;
        }
        {
            float sy  = fmaxf((Y1 + 0.5f) * 14.0f / dimE - 0.5f, 0.0f);
            float r0f = floorf(sy);
            int r0 = (int)r0f;
            int r1 = min(r0 + 1, 13);
            t_f1[w][axis][idx]  = sy - r0f;
            t_i10[w][axis][idx] = r0 * mul;
            t_i11[w][axis][idx] = r1 * mul;
        }
    }
    __syncwarp();

    for (int t = lane; t < 196; t += 32) {
        const int y = t / 14;
        const int x = t - y * 14;

        float wy  = t_w[w][0][y];
        float wx  = t_w[w][1][x];
        float fyA = t_f0[w][0][y], fyB = t_f1[w][0][y];
        float fxA = t_f0[w][1][x], fxB = t_f1[w][1][x];
        int rA0 = t_i00[w][0][y], rA1 = t_i01[w][0][y];
        int rB0 = t_i10[w][0][y], rB1 = t_i11[w][0][y];
        int cA0 = t_i00[w][1][x], cA1 = t_i01[w][1][x];
        int cB0 = t_i10[w][1][x], cB1 = t_i11[w][1][x];

        float v00 = bilin_combine(m14[w], rA0, rA1, cA0, cA1, fyA, fxA);
        float v01 = bilin_combine(m14[w], rA0, rA1, cB0, cB1, fyA, fxB);
        float v10 = bilin_combine(m14[w], rB0, rB1, cA0, cA1, fyB, fxA);
        float v11 = bilin_combine(m14[w], rB0, rB1, cB0, cB1, fyB, fxB);

        cm[w][t] = v00 * (1.0f - wy) * (1.0f - wx)
                 + v01 * (1.0f - wy) * wx
                 + v10 * wy * (1.0f - wx)
                 + v11 * wy * wx;
    }
    __syncwarp();

    for (int t = lane; t < 49; t += 32) {
        const int qy = t / 7;
        const int qx = t - qy * 7;
        const float* c = cm[w];
        float s = (c[(2 * qy) * 14 + 2 * qx] + c[(2 * qy) * 14 + 2 * qx + 1]
                 + c[(2 * qy + 1) * 14 + 2 * qx] + c[(2 * qy + 1) * 14 + 2 * qx + 1]) * 0.25f;
        key[w][t] = ((unsigned long long)__float_as_uint(s) << 6)
                  | (unsigned long long)(48 - t);
    }
    __syncwarp();

    for (int t = lane; t < 49; t += 32) {
        const unsigned long long kv = key[w][t];
        int rank = 0;
        #pragma unroll
        for (int j = 0; j < 49; ++j)
            rank += (key[w][j] > kv);
        keep[w][t] = (rank < 25);
    }
    __syncwarp();

    for (int t = lane; t < 196; t += 32) {
        const int y = t / 14;
        const int x = t - y * 14;
        const int q = (y >> 1) * 7 + (x >> 1);
        mask_out[(box * BS_N + i) * 196 + t] = keep[w][q] ? 0.0f : 1.0f;
    }
}

// ---------------------------------------------------------------------------
// Launch: split -> gemm on main branch; mask forked, enqueued last so it
// backfills the gemm's wave tail.
// ---------------------------------------------------------------------------
extern "C" void kernel_launch(void* const* d_in, const int* in_sizes, int n_in,
                              void* d_out, int out_size) {
    const float* attn        = (const float*)d_in[0];   // [8192, 196]
    const int*   pos         = (const int*)d_in[1];     // [8192, 3, 4]
    const float* image_embed = (const float*)d_in[2];   // [16384, 768]
    const float* Wm          = (const float*)d_in[3];   // [400, 768]
    const float* bias        = (const float*)d_in[4];   // [400]

    float* logits = (float*)d_out;                      // [16384, 400]
    float* mask   = (float*)d_out + LOGITS_ELEMS;       // [16384, 196]

    cudaFuncSetAttribute(gemm_hmma_kernel,
                         cudaFuncAttributeMaxDynamicSharedMemorySize,
                         SMEM_GEMM_TOTAL);

    cudaStream_t s2 = nullptr;
    cudaEvent_t  e1 = nullptr, e2 = nullptr;
    bool forked =
        (cudaStreamCreateWithFlags(&s2, cudaStreamNonBlocking) == cudaSuccess) &&
        (cudaEventCreateWithFlags(&e1, cudaEventDisableTiming) == cudaSuccess) &&
        (cudaEventCreateWithFlags(&e2, cudaEventDisableTiming) == cudaSuccess);

    if (forked) {
        forked = (cudaEventRecord(e1, (cudaStream_t)0) == cudaSuccess) &&
                 (cudaStreamWaitEvent(s2, e1, 0) == cudaSuccess);
    }

    split_kernel<<<(SPLIT_GROUPS + 255) / 256, 256>>>(image_embed, Wm);
    dim3 ggrid(NUM_CLASSES / BN, M_TOTAL / BM);
    gemm_hmma_kernel<<<ggrid, 256, SMEM_GEMM_TOTAL>>>(bias, logits);

    if (forked) {
        mask_kernel<<<(2 * BS_N) / MW_WARPS, 256, 0, s2>>>(attn, pos, mask);
        cudaEventRecord(e2, s2);
        cudaStreamWaitEvent((cudaStream_t)0, e2, 0);
    } else {
        mask_kernel<<<(2 * BS_N) / MW_WARPS, 256>>>(attn, pos, mask);
    }
}